// round 5
// baseline (speedup 1.0000x reference)
#include <cuda_runtime.h>

#define NNODES 50000
#define NEDGES 320000
#define OUT_V_OFF 3200000
#define SC_S_OFF  12800000
#define SC_V_OFF  16000000

// ---- scratch (__device__ globals: allocation-free) ----
__device__ float g_s_scr[NNODES * 64];
__device__ float g_v_scr[NNODES * 192];   // [n][x][c]
__device__ float g_ms[NNODES * 128];      // [n][2C]
__device__ float g_mv[NNODES * 576];      // [n][x][3C]

__device__ __forceinline__ float silu_f(float x) { return x / (1.0f + __expf(-x)); }

__device__ __forceinline__ void red4(float* p, float4 v) {
    atomicAdd(p + 0, v.x); atomicAdd(p + 1, v.y);
    atomicAdd(p + 2, v.z); atomicAdd(p + 3, v.w);
}
__device__ __forceinline__ float4 f4mul(float4 a, float4 b) {
    return make_float4(a.x*b.x, a.y*b.y, a.z*b.z, a.w*b.w);
}
__device__ __forceinline__ float4 f4muls(float4 a, float s) {
    return make_float4(a.x*s, a.y*s, a.z*s, a.w*s);
}
__device__ __forceinline__ float4 f4sub(float4 a, float4 b) {
    return make_float4(a.x-b.x, a.y-b.y, a.z-b.z, a.w-b.w);
}
__device__ __forceinline__ float4 f4add(float4 a, float4 b) {
    return make_float4(a.x+b.x, a.y+b.y, a.z+b.z, a.w+b.w);
}

// 4-node x 4-d register-tile GEMM. A: [K][68] node-contig padded, W: [K][64].
template <int K>
__device__ __forceinline__ void gemm_tile(const float* __restrict__ A,
                                          const float* __restrict__ W,
                                          float Y[4][4]) {
#pragma unroll
    for (int i = 0; i < 4; i++)
#pragma unroll
        for (int j = 0; j < 4; j++) Y[i][j] = 0.0f;
#pragma unroll 8
    for (int c = 0; c < K; c++) {
        float4 a = *(const float4*)(A + c * 68);
        float4 w = *(const float4*)(W + c * 64);
        Y[0][0]+=a.x*w.x; Y[0][1]+=a.x*w.y; Y[0][2]+=a.x*w.z; Y[0][3]+=a.x*w.w;
        Y[1][0]+=a.y*w.x; Y[1][1]+=a.y*w.y; Y[1][2]+=a.y*w.z; Y[1][3]+=a.y*w.w;
        Y[2][0]+=a.z*w.x; Y[2][1]+=a.z*w.y; Y[2][2]+=a.z*w.z; Y[2][3]+=a.z*w.w;
        Y[3][0]+=a.w*w.x; Y[3][1]+=a.w*w.y; Y[3][2]+=a.w*w.z; Y[3][3]+=a.w*w.w;
    }
}

// ===================== K0: zero scratch =====================
__global__ void zero_kernel() {
    long i = (long)blockIdx.x * blockDim.x + threadIdx.x;
    long t = (long)gridDim.x * blockDim.x;
    float4 z = make_float4(0.f, 0.f, 0.f, 0.f);
    for (long j = i; j < (long)NNODES * 128 / 4; j += t) ((float4*)g_ms)[j] = z;
    for (long j = i; j < (long)NNODES * 576 / 4; j += t) ((float4*)g_mv)[j] = z;
}

// ===================== K1: node side =====================
// smem floats: fsm[64][68]@0 | fvm[3][64][68]@4352 | wbuf[64][64]@17408 | attr[64][10]@21504
#define K1_SMEM_BYTES (22144 * 4)
__global__ void __launch_bounds__(256) node_kernel(
    const float* __restrict__ attrs_g, const float* __restrict__ fs_g,
    const float* __restrict__ fv_g,
    const float* __restrict__ Wscs, const float* __restrict__ Wscv,
    const float* __restrict__ Wses, const float* __restrict__ Wsev,
    float* __restrict__ out) {
    extern __shared__ float sm[];
    float* fsm = sm;
    float* fvm = sm + 4352;
    float* wbuf = sm + 17408;
    float* atm = sm + 21504;
    const int tid = threadIdx.x;
    const int n0 = blockIdx.x * 64;

    for (int idx = tid; idx < 4096; idx += 256) {
        int n = idx >> 6, c = idx & 63, gn = n0 + n;
        fsm[c * 68 + n] = (gn < NNODES) ? fs_g[gn * 64 + c] : 0.0f;
    }
    for (int idx = tid; idx < 12288; idx += 256) {
        int n = idx / 192, r = idx - n * 192, c = r / 3, x = r - c * 3, gn = n0 + n;
        fvm[x * 4352 + c * 68 + n] = (gn < NNODES) ? fv_g[gn * 192 + c * 3 + x] : 0.0f;
    }
    for (int idx = tid; idx < 640; idx += 256) {
        int n = idx / 10, gn = n0 + n;
        atm[idx] = (gn < NNODES) ? attrs_g[gn * 10 + (idx - n * 10)] : 0.0f;
    }

    const int tx = tid & 15, ty = tid >> 4;
    const int nb = ty * 4, db = tx * 4;
    float acc_s[4][4], acc_v[3][4][4], Y[4][4];
#pragma unroll
    for (int i = 0; i < 4; i++)
#pragma unroll
        for (int j = 0; j < 4; j++) acc_s[i][j] = 0.0f;
#pragma unroll
    for (int x = 0; x < 3; x++)
#pragma unroll
        for (int i = 0; i < 4; i++)
#pragma unroll
            for (int j = 0; j < 4; j++) acc_v[x][i][j] = 0.0f;

    // scalar skip-TP: 10 attr passes
    for (int a = 0; a < 10; a++) {
        __syncthreads();
        for (int idx = tid; idx < 4096; idx += 256)
            wbuf[idx] = Wscs[((idx >> 6) * 10 + a) * 64 + (idx & 63)];
        __syncthreads();
        gemm_tile<64>(fsm + nb, wbuf + db, Y);
#pragma unroll
        for (int i = 0; i < 4; i++) {
            float av = atm[(nb + i) * 10 + a];
#pragma unroll
            for (int j = 0; j < 4; j++) acc_s[i][j] += av * Y[i][j];
        }
    }
    // vector skip-TP: 10 attr passes x 3 components
    for (int a = 0; a < 10; a++) {
        __syncthreads();
        for (int idx = tid; idx < 4096; idx += 256)
            wbuf[idx] = Wscv[((idx >> 6) * 10 + a) * 64 + (idx & 63)];
        __syncthreads();
#pragma unroll 1
        for (int x = 0; x < 3; x++) {
            gemm_tile<64>(fvm + x * 4352 + nb, wbuf + db, Y);
#pragma unroll
            for (int i = 0; i < 4; i++) {
                float av = atm[(nb + i) * 10 + a];
#pragma unroll
                for (int j = 0; j < 4; j++) acc_v[x][i][j] += av * Y[i][j];
            }
        }
    }
    // self linear (scalar)
    __syncthreads();
    for (int idx = tid; idx < 4096; idx += 256) wbuf[idx] = Wses[idx];
    __syncthreads();
    gemm_tile<64>(fsm + nb, wbuf + db, Y);
#pragma unroll
    for (int i = 0; i < 4; i++) {
        int gn = n0 + nb + i;
        if (gn < NNODES)
            *(float4*)(g_s_scr + gn * 64 + db) =
                make_float4(Y[i][0]*0.125f, Y[i][1]*0.125f, Y[i][2]*0.125f, Y[i][3]*0.125f);
    }
    // self linear (vector)
    __syncthreads();
    for (int idx = tid; idx < 4096; idx += 256) wbuf[idx] = Wsev[idx];
    __syncthreads();
#pragma unroll 1
    for (int x = 0; x < 3; x++) {
        gemm_tile<64>(fvm + x * 4352 + nb, wbuf + db, Y);
#pragma unroll
        for (int i = 0; i < 4; i++) {
            int gn = n0 + nb + i;
            if (gn < NNODES)
                *(float4*)(g_v_scr + gn * 192 + x * 64 + db) =
                    make_float4(Y[i][0]*0.125f, Y[i][1]*0.125f, Y[i][2]*0.125f, Y[i][3]*0.125f);
        }
    }
    // skip-connection outputs
    const float isc = rsqrtf(640.0f);
#pragma unroll
    for (int i = 0; i < 4; i++) {
        int gn = n0 + nb + i;
        if (gn < NNODES) {
            *(float4*)(out + SC_S_OFF + gn * 64 + db) =
                make_float4(acc_s[i][0]*isc, acc_s[i][1]*isc, acc_s[i][2]*isc, acc_s[i][3]*isc);
#pragma unroll
            for (int j = 0; j < 4; j++)
#pragma unroll
                for (int x = 0; x < 3; x++)
                    out[SC_V_OFF + (gn * 64 + db + j) * 3 + x] = acc_v[x][i][j] * isc;
        }
    }
}

// ===================== K2: edge side =====================
// smem floats: W1s@0(512) W2s@512(4096) W3s@4608(4096) W4s@8704(20480) hsm@29184(16384)
#define K2_SMEM_BYTES (45568 * 4)

__device__ __forceinline__ void mlp_layer(const float* __restrict__ Wsm,
                                          const float h_in[64],
                                          float* __restrict__ hsm, int tid,
                                          float scale) {
#pragma unroll 1
    for (int dg = 0; dg < 16; dg++) {
        float4 acc = make_float4(0.f, 0.f, 0.f, 0.f);
#pragma unroll
        for (int c = 0; c < 64; c++) {
            float4 w = *(const float4*)(Wsm + c * 64 + dg * 4);
            float hc = h_in[c];
            acc.x += hc*w.x; acc.y += hc*w.y; acc.z += hc*w.z; acc.w += hc*w.w;
        }
        hsm[(dg*4+0)*256+tid] = silu_f(acc.x*scale);
        hsm[(dg*4+1)*256+tid] = silu_f(acc.y*scale);
        hsm[(dg*4+2)*256+tid] = silu_f(acc.z*scale);
        hsm[(dg*4+3)*256+tid] = silu_f(acc.w*scale);
    }
}

__device__ __forceinline__ float4 gemv4(const float* __restrict__ W4s,
                                        const float h[64], int col) {
    float4 a = make_float4(0.f, 0.f, 0.f, 0.f);
#pragma unroll
    for (int k = 0; k < 64; k++) {
        float4 t = *(const float4*)(W4s + k * 320 + col);
        float hk = h[k];
        a.x += hk*t.x; a.y += hk*t.y; a.z += hk*t.z; a.w += hk*t.w;
    }
    return a;
}

__global__ void __launch_bounds__(256) edge_kernel(
    const float* __restrict__ ef_g, const float* __restrict__ sh0_g,
    const float* __restrict__ sh1_g, const int* __restrict__ snd_g,
    const int* __restrict__ rcv_g,
    const float* __restrict__ W1, const float* __restrict__ W2,
    const float* __restrict__ W3, const float* __restrict__ W4) {
    extern __shared__ float sm[];
    float* W1s = sm;
    float* W2s = sm + 512;
    float* W3s = sm + 4608;
    float* W4s = sm + 8704;
    float* hsm = sm + 29184;
    const int tid = threadIdx.x;

    for (int i = tid; i < 512; i += 256) W1s[i] = W1[i];
    for (int i = tid; i < 4096; i += 256) W2s[i] = W2[i];
    for (int i = tid; i < 4096; i += 256) W3s[i] = W3[i];
    for (int i = tid; i < 20480; i += 256) W4s[i] = W4[i];
    __syncthreads();

    const int e = blockIdx.x * 256 + tid;  // E divisible by 256
    float efr[8];
    {
        float4 t0 = *(const float4*)(ef_g + e * 8);
        float4 t1 = *(const float4*)(ef_g + e * 8 + 4);
        efr[0]=t0.x; efr[1]=t0.y; efr[2]=t0.z; efr[3]=t0.w;
        efr[4]=t1.x; efr[5]=t1.y; efr[6]=t1.z; efr[7]=t1.w;
    }
    // layer 1 (8 -> 64)
    const float invs8 = rsqrtf(8.0f);
#pragma unroll 1
    for (int dg = 0; dg < 16; dg++) {
        float4 acc = make_float4(0.f, 0.f, 0.f, 0.f);
#pragma unroll
        for (int j = 0; j < 8; j++) {
            float4 w = *(const float4*)(W1s + j * 64 + dg * 4);
            float ej = efr[j];
            acc.x += ej*w.x; acc.y += ej*w.y; acc.z += ej*w.z; acc.w += ej*w.w;
        }
        hsm[(dg*4+0)*256+tid] = silu_f(acc.x*invs8);
        hsm[(dg*4+1)*256+tid] = silu_f(acc.y*invs8);
        hsm[(dg*4+2)*256+tid] = silu_f(acc.z*invs8);
        hsm[(dg*4+3)*256+tid] = silu_f(acc.w*invs8);
    }
    float h[64];
#pragma unroll
    for (int c = 0; c < 64; c++) h[c] = hsm[c * 256 + tid];
    mlp_layer(W2s, h, hsm, tid, 0.125f);
#pragma unroll
    for (int c = 0; c < 64; c++) h[c] = hsm[c * 256 + tid];
    mlp_layer(W3s, h, hsm, tid, 0.125f);
#pragma unroll
    for (int c = 0; c < 64; c++) h[c] = hsm[c * 256 + tid];

    const int s = snd_g[e];
    const int r = rcv_g[e];
    const float sh0v = sh0_g[e];
    float q[3];
    q[0] = sh1_g[e*3+0]; q[1] = sh1_g[e*3+1]; q[2] = sh1_g[e*3+2];
    const float* sb = g_s_scr + s * 64;
    const float* vb = g_v_scr + s * 192;
    float* msb = g_ms + r * 128;
    float* mvb = g_mv + r * 576;
    const float i3 = rsqrtf(3.0f), i2 = rsqrtf(2.0f);

#pragma unroll 1
    for (int cg = 0; cg < 16; cg++) {
        const int c4 = cg * 4;
        float4 w1v = f4muls(gemv4(W4s, h, c4), 0.125f);
        float4 w2v = f4muls(gemv4(W4s, h, 64 + c4), 0.125f);
        float4 w3v = f4muls(gemv4(W4s, h, 128 + c4), 0.125f);
        float4 w4v = f4muls(gemv4(W4s, h, 192 + c4), 0.125f);
        float4 w5v = f4muls(gemv4(W4s, h, 256 + c4), 0.125f);

        float4 se = *(const float4*)(sb + c4);
        float4 vv[3];
        vv[0] = *(const float4*)(vb + c4);
        vv[1] = *(const float4*)(vb + 64 + c4);
        vv[2] = *(const float4*)(vb + 128 + c4);

        red4(msb + c4, f4muls(f4mul(w1v, se), sh0v));
        float4 dt = f4add(f4add(f4muls(vv[0], q[0]), f4muls(vv[1], q[1])),
                          f4muls(vv[2], q[2]));
        red4(msb + 64 + c4, f4muls(f4mul(w2v, dt), i3));
#pragma unroll
        for (int x = 0; x < 3; x++) {
            const int x1 = (x + 1) % 3, x2 = (x + 2) % 3;
            float4 cr = f4sub(f4muls(vv[x1], q[x2]), f4muls(vv[x2], q[x1]));
            red4(mvb + x*192 + c4,       f4muls(f4mul(w3v, se), q[x]));
            red4(mvb + x*192 + 64 + c4,  f4muls(f4mul(w4v, vv[x]), sh0v));
            red4(mvb + x*192 + 128 + c4, f4muls(f4mul(w5v, cr), i2));
        }
    }
}

// ===================== K3: output linear =====================
// smem floats: msm[192][68]@0 (13056) | wbuf[192][64]@13056 (12288)
#define K3_SMEM_BYTES (25344 * 4)
__global__ void __launch_bounds__(256) out_kernel(
    const float* __restrict__ Wouts, const float* __restrict__ Woutv,
    float* __restrict__ out) {
    extern __shared__ float sm[];
    float* msm = sm;
    float* wbuf = sm + 13056;
    const int tid = threadIdx.x;
    const int n0 = blockIdx.x * 64;
    const int tx = tid & 15, ty = tid >> 4;
    const int nb = ty * 4, db = tx * 4;
    float Y[4][4];

    // scalar: m_s[128] @ W_out_s[128,64]
    for (int idx = tid; idx < 8192; idx += 256) {
        int n = idx >> 7, k = idx & 127, gn = n0 + n;
        msm[k * 68 + n] = (gn < NNODES) ? g_ms[gn * 128 + k] : 0.0f;
    }
    for (int idx = tid; idx < 8192; idx += 256) wbuf[idx] = Wouts[idx];
    __syncthreads();
    gemm_tile<128>(msm + nb, wbuf + db, Y);
    const float ss = rsqrtf(128.0f) / 16.0f;
#pragma unroll
    for (int i = 0; i < 4; i++) {
        int gn = n0 + nb + i;
        if (gn < NNODES)
            *(float4*)(out + gn * 64 + db) =
                make_float4(Y[i][0]*ss, Y[i][1]*ss, Y[i][2]*ss, Y[i][3]*ss);
    }
    // vector: m_v[x][192] @ W_out_v[192,64], 3 passes
    __syncthreads();
    for (int idx = tid; idx < 12288; idx += 256) wbuf[idx] = Woutv[idx];
    const float sv = rsqrtf(192.0f) / 16.0f;
#pragma unroll 1
    for (int x = 0; x < 3; x++) {
        __syncthreads();
        for (int idx = tid; idx < 12288; idx += 256) {
            int n = idx / 192, k = idx - n * 192, gn = n0 + n;
            msm[k * 68 + n] = (gn < NNODES) ? g_mv[gn * 576 + x * 192 + k] : 0.0f;
        }
        __syncthreads();
        gemm_tile<192>(msm + nb, wbuf + db, Y);
#pragma unroll
        for (int i = 0; i < 4; i++) {
            int gn = n0 + nb + i;
            if (gn < NNODES)
#pragma unroll
                for (int j = 0; j < 4; j++)
                    out[OUT_V_OFF + gn * 192 + (db + j) * 3 + x] = Y[i][j] * sv;
        }
    }
}

// ===================== launch =====================
extern "C" void kernel_launch(void* const* d_in, const int* in_sizes, int n_in,
                              void* d_out, int out_size) {
    const float* attrs = (const float*)d_in[0];
    const float* fs    = (const float*)d_in[1];
    const float* fv    = (const float*)d_in[2];
    const float* sh0   = (const float*)d_in[3];
    const float* sh1   = (const float*)d_in[4];
    const float* ef    = (const float*)d_in[5];
    const int*   snd   = (const int*)d_in[6];
    const int*   rcv   = (const int*)d_in[7];
    const float* Wscs  = (const float*)d_in[8];
    const float* Wscv  = (const float*)d_in[9];
    const float* Wses  = (const float*)d_in[10];
    const float* Wsev  = (const float*)d_in[11];
    const float* W1    = (const float*)d_in[12];
    const float* W2    = (const float*)d_in[13];
    const float* W3    = (const float*)d_in[14];
    const float* W4    = (const float*)d_in[15];
    const float* Wouts = (const float*)d_in[16];
    const float* Woutv = (const float*)d_in[17];
    float* out = (float*)d_out;

    cudaFuncSetAttribute(node_kernel, cudaFuncAttributeMaxDynamicSharedMemorySize, K1_SMEM_BYTES);
    cudaFuncSetAttribute(edge_kernel, cudaFuncAttributeMaxDynamicSharedMemorySize, K2_SMEM_BYTES);
    cudaFuncSetAttribute(out_kernel,  cudaFuncAttributeMaxDynamicSharedMemorySize, K3_SMEM_BYTES);

    zero_kernel<<<1024, 256>>>();
    node_kernel<<<(NNODES + 63) / 64, 256, K1_SMEM_BYTES>>>(
        attrs, fs, fv, Wscs, Wscv, Wses, Wsev, out);
    edge_kernel<<<NEDGES / 256, 256, K2_SMEM_BYTES>>>(
        ef, sh0, sh1, snd, rcv, W1, W2, W3, W4);
    out_kernel<<<(NNODES + 63) / 64, 256, K3_SMEM_BYTES>>>(Wouts, Woutv, out);
}

// round 6
// speedup vs baseline: 1.3420x; 1.3420x over previous
#include <cuda_runtime.h>

#define NNODES 50000
#define NEDGES 320000
#define OUT_V_OFF 3200000
#define SC_S_OFF  12800000
#define SC_V_OFF  16000000

// ---- scratch (__device__ globals: allocation-free) ----
__device__ float g_s_scr[NNODES * 64];
__device__ float g_v_scr[NNODES * 192];   // [n][x][c]
__device__ float g_ms[NNODES * 128];      // [n][2C]
__device__ float g_mv[NNODES * 576];      // [n][3C][3]  (x innermost!)

__device__ __forceinline__ float silu_f(float x) { return x / (1.0f + __expf(-x)); }

// vectorized f32 reduction (sm_90+): one instruction, one 16B L2 atomic op
__device__ __forceinline__ void red4v(float* p, float4 v) {
    asm volatile("red.global.add.v4.f32 [%0], {%1, %2, %3, %4};"
                 :: "l"(p), "f"(v.x), "f"(v.y), "f"(v.z), "f"(v.w) : "memory");
}

__device__ __forceinline__ float4 f4mul(float4 a, float4 b) {
    return make_float4(a.x*b.x, a.y*b.y, a.z*b.z, a.w*b.w);
}
__device__ __forceinline__ float4 f4muls(float4 a, float s) {
    return make_float4(a.x*s, a.y*s, a.z*s, a.w*s);
}
__device__ __forceinline__ float4 f4sub(float4 a, float4 b) {
    return make_float4(a.x-b.x, a.y-b.y, a.z-b.z, a.w-b.w);
}
__device__ __forceinline__ float4 f4add(float4 a, float4 b) {
    return make_float4(a.x+b.x, a.y+b.y, a.z+b.z, a.w+b.w);
}

// scatter 12 contiguous floats (4 channels x 3 xyz, x innermost) as 3 v4 reds.
// t[x] components .x..w = channels 0..3.
__device__ __forceinline__ void scatter12(float* p, const float4 t[3]) {
    red4v(p + 0, make_float4(t[0].x, t[1].x, t[2].x, t[0].y));
    red4v(p + 4, make_float4(t[1].y, t[2].y, t[0].z, t[1].z));
    red4v(p + 8, make_float4(t[2].z, t[0].w, t[1].w, t[2].w));
}

// 4-node x 4-d register-tile GEMM. A: [K][68] node-contig padded, W: [K][64].
template <int K>
__device__ __forceinline__ void gemm_tile(const float* __restrict__ A,
                                          const float* __restrict__ W,
                                          float Y[4][4]) {
#pragma unroll
    for (int i = 0; i < 4; i++)
#pragma unroll
        for (int j = 0; j < 4; j++) Y[i][j] = 0.0f;
#pragma unroll 8
    for (int c = 0; c < K; c++) {
        float4 a = *(const float4*)(A + c * 68);
        float4 w = *(const float4*)(W + c * 64);
        Y[0][0]+=a.x*w.x; Y[0][1]+=a.x*w.y; Y[0][2]+=a.x*w.z; Y[0][3]+=a.x*w.w;
        Y[1][0]+=a.y*w.x; Y[1][1]+=a.y*w.y; Y[1][2]+=a.y*w.z; Y[1][3]+=a.y*w.w;
        Y[2][0]+=a.z*w.x; Y[2][1]+=a.z*w.y; Y[2][2]+=a.z*w.z; Y[2][3]+=a.z*w.w;
        Y[3][0]+=a.w*w.x; Y[3][1]+=a.w*w.y; Y[3][2]+=a.w*w.z; Y[3][3]+=a.w*w.w;
    }
}

// ===================== K0: zero scratch =====================
__global__ void zero_kernel() {
    long i = (long)blockIdx.x * blockDim.x + threadIdx.x;
    long t = (long)gridDim.x * blockDim.x;
    float4 z = make_float4(0.f, 0.f, 0.f, 0.f);
    for (long j = i; j < (long)NNODES * 128 / 4; j += t) ((float4*)g_ms)[j] = z;
    for (long j = i; j < (long)NNODES * 576 / 4; j += t) ((float4*)g_mv)[j] = z;
}

// ===================== K1: node side =====================
// smem floats: fsm[64][68]@0 | fvm[3][64][68]@4352 | wbuf[64][64]@17408 | attr[64][10]@21504
#define K1_SMEM_BYTES (22144 * 4)
__global__ void __launch_bounds__(256) node_kernel(
    const float* __restrict__ attrs_g, const float* __restrict__ fs_g,
    const float* __restrict__ fv_g,
    const float* __restrict__ Wscs, const float* __restrict__ Wscv,
    const float* __restrict__ Wses, const float* __restrict__ Wsev,
    float* __restrict__ out) {
    extern __shared__ float sm[];
    float* fsm = sm;
    float* fvm = sm + 4352;
    float* wbuf = sm + 17408;
    float* atm = sm + 21504;
    const int tid = threadIdx.x;
    const int n0 = blockIdx.x * 64;

    for (int idx = tid; idx < 4096; idx += 256) {
        int n = idx >> 6, c = idx & 63, gn = n0 + n;
        fsm[c * 68 + n] = (gn < NNODES) ? fs_g[gn * 64 + c] : 0.0f;
    }
    for (int idx = tid; idx < 12288; idx += 256) {
        int n = idx / 192, r = idx - n * 192, c = r / 3, x = r - c * 3, gn = n0 + n;
        fvm[x * 4352 + c * 68 + n] = (gn < NNODES) ? fv_g[gn * 192 + c * 3 + x] : 0.0f;
    }
    for (int idx = tid; idx < 640; idx += 256) {
        int n = idx / 10, gn = n0 + n;
        atm[idx] = (gn < NNODES) ? attrs_g[gn * 10 + (idx - n * 10)] : 0.0f;
    }

    const int tx = tid & 15, ty = tid >> 4;
    const int nb = ty * 4, db = tx * 4;
    float acc_s[4][4], acc_v[3][4][4], Y[4][4];
#pragma unroll
    for (int i = 0; i < 4; i++)
#pragma unroll
        for (int j = 0; j < 4; j++) acc_s[i][j] = 0.0f;
#pragma unroll
    for (int x = 0; x < 3; x++)
#pragma unroll
        for (int i = 0; i < 4; i++)
#pragma unroll
            for (int j = 0; j < 4; j++) acc_v[x][i][j] = 0.0f;

    for (int a = 0; a < 10; a++) {
        __syncthreads();
        for (int idx = tid; idx < 4096; idx += 256)
            wbuf[idx] = Wscs[((idx >> 6) * 10 + a) * 64 + (idx & 63)];
        __syncthreads();
        gemm_tile<64>(fsm + nb, wbuf + db, Y);
#pragma unroll
        for (int i = 0; i < 4; i++) {
            float av = atm[(nb + i) * 10 + a];
#pragma unroll
            for (int j = 0; j < 4; j++) acc_s[i][j] += av * Y[i][j];
        }
    }
    for (int a = 0; a < 10; a++) {
        __syncthreads();
        for (int idx = tid; idx < 4096; idx += 256)
            wbuf[idx] = Wscv[((idx >> 6) * 10 + a) * 64 + (idx & 63)];
        __syncthreads();
#pragma unroll 1
        for (int x = 0; x < 3; x++) {
            gemm_tile<64>(fvm + x * 4352 + nb, wbuf + db, Y);
#pragma unroll
            for (int i = 0; i < 4; i++) {
                float av = atm[(nb + i) * 10 + a];
#pragma unroll
                for (int j = 0; j < 4; j++) acc_v[x][i][j] += av * Y[i][j];
            }
        }
    }
    __syncthreads();
    for (int idx = tid; idx < 4096; idx += 256) wbuf[idx] = Wses[idx];
    __syncthreads();
    gemm_tile<64>(fsm + nb, wbuf + db, Y);
#pragma unroll
    for (int i = 0; i < 4; i++) {
        int gn = n0 + nb + i;
        if (gn < NNODES)
            *(float4*)(g_s_scr + gn * 64 + db) =
                make_float4(Y[i][0]*0.125f, Y[i][1]*0.125f, Y[i][2]*0.125f, Y[i][3]*0.125f);
    }
    __syncthreads();
    for (int idx = tid; idx < 4096; idx += 256) wbuf[idx] = Wsev[idx];
    __syncthreads();
#pragma unroll 1
    for (int x = 0; x < 3; x++) {
        gemm_tile<64>(fvm + x * 4352 + nb, wbuf + db, Y);
#pragma unroll
        for (int i = 0; i < 4; i++) {
            int gn = n0 + nb + i;
            if (gn < NNODES)
                *(float4*)(g_v_scr + gn * 192 + x * 64 + db) =
                    make_float4(Y[i][0]*0.125f, Y[i][1]*0.125f, Y[i][2]*0.125f, Y[i][3]*0.125f);
        }
    }
    const float isc = rsqrtf(640.0f);
#pragma unroll
    for (int i = 0; i < 4; i++) {
        int gn = n0 + nb + i;
        if (gn < NNODES) {
            *(float4*)(out + SC_S_OFF + gn * 64 + db) =
                make_float4(acc_s[i][0]*isc, acc_s[i][1]*isc, acc_s[i][2]*isc, acc_s[i][3]*isc);
#pragma unroll
            for (int j = 0; j < 4; j++)
#pragma unroll
                for (int x = 0; x < 3; x++)
                    out[SC_V_OFF + (gn * 64 + db + j) * 3 + x] = acc_v[x][i][j] * isc;
        }
    }
}

// ===================== K2: edge side =====================
// smem floats: W1s@0(512) W2s@512(4096) W3s@4608(4096) W4s@8704(20480) hsm@29184(16384)
#define K2_SMEM_BYTES (45568 * 4)

__device__ __forceinline__ void mlp_layer(const float* __restrict__ Wsm,
                                          const float h_in[64],
                                          float* __restrict__ hsm, int tid,
                                          float scale) {
#pragma unroll 1
    for (int dg = 0; dg < 16; dg++) {
        float4 acc = make_float4(0.f, 0.f, 0.f, 0.f);
#pragma unroll
        for (int c = 0; c < 64; c++) {
            float4 w = *(const float4*)(Wsm + c * 64 + dg * 4);
            float hc = h_in[c];
            acc.x += hc*w.x; acc.y += hc*w.y; acc.z += hc*w.z; acc.w += hc*w.w;
        }
        hsm[(dg*4+0)*256+tid] = silu_f(acc.x*scale);
        hsm[(dg*4+1)*256+tid] = silu_f(acc.y*scale);
        hsm[(dg*4+2)*256+tid] = silu_f(acc.z*scale);
        hsm[(dg*4+3)*256+tid] = silu_f(acc.w*scale);
    }
}

__device__ __forceinline__ float4 gemv4(const float* __restrict__ W4s,
                                        const float h[64], int col) {
    float4 a = make_float4(0.f, 0.f, 0.f, 0.f);
#pragma unroll
    for (int k = 0; k < 64; k++) {
        float4 t = *(const float4*)(W4s + k * 320 + col);
        float hk = h[k];
        a.x += hk*t.x; a.y += hk*t.y; a.z += hk*t.z; a.w += hk*t.w;
    }
    return a;
}

__global__ void __launch_bounds__(256) edge_kernel(
    const float* __restrict__ ef_g, const float* __restrict__ sh0_g,
    const float* __restrict__ sh1_g, const int* __restrict__ snd_g,
    const int* __restrict__ rcv_g,
    const float* __restrict__ W1, const float* __restrict__ W2,
    const float* __restrict__ W3, const float* __restrict__ W4) {
    extern __shared__ float sm[];
    float* W1s = sm;
    float* W2s = sm + 512;
    float* W3s = sm + 4608;
    float* W4s = sm + 8704;
    float* hsm = sm + 29184;
    const int tid = threadIdx.x;

    for (int i = tid; i < 512; i += 256) W1s[i] = W1[i];
    for (int i = tid; i < 4096; i += 256) W2s[i] = W2[i];
    for (int i = tid; i < 4096; i += 256) W3s[i] = W3[i];
    for (int i = tid; i < 20480; i += 256) W4s[i] = W4[i];
    __syncthreads();

    const int e = blockIdx.x * 256 + tid;  // E divisible by 256
    float efr[8];
    {
        float4 t0 = *(const float4*)(ef_g + e * 8);
        float4 t1 = *(const float4*)(ef_g + e * 8 + 4);
        efr[0]=t0.x; efr[1]=t0.y; efr[2]=t0.z; efr[3]=t0.w;
        efr[4]=t1.x; efr[5]=t1.y; efr[6]=t1.z; efr[7]=t1.w;
    }
    const float invs8 = rsqrtf(8.0f);
#pragma unroll 1
    for (int dg = 0; dg < 16; dg++) {
        float4 acc = make_float4(0.f, 0.f, 0.f, 0.f);
#pragma unroll
        for (int j = 0; j < 8; j++) {
            float4 w = *(const float4*)(W1s + j * 64 + dg * 4);
            float ej = efr[j];
            acc.x += ej*w.x; acc.y += ej*w.y; acc.z += ej*w.z; acc.w += ej*w.w;
        }
        hsm[(dg*4+0)*256+tid] = silu_f(acc.x*invs8);
        hsm[(dg*4+1)*256+tid] = silu_f(acc.y*invs8);
        hsm[(dg*4+2)*256+tid] = silu_f(acc.z*invs8);
        hsm[(dg*4+3)*256+tid] = silu_f(acc.w*invs8);
    }
    float h[64];
#pragma unroll
    for (int c = 0; c < 64; c++) h[c] = hsm[c * 256 + tid];
    mlp_layer(W2s, h, hsm, tid, 0.125f);
#pragma unroll
    for (int c = 0; c < 64; c++) h[c] = hsm[c * 256 + tid];
    mlp_layer(W3s, h, hsm, tid, 0.125f);
#pragma unroll
    for (int c = 0; c < 64; c++) h[c] = hsm[c * 256 + tid];

    const int s = snd_g[e];
    const int r = rcv_g[e];
    const float sh0v = sh0_g[e];
    float q[3];
    q[0] = sh1_g[e*3+0]; q[1] = sh1_g[e*3+1]; q[2] = sh1_g[e*3+2];
    const float* sb = g_s_scr + s * 64;
    const float* vb = g_v_scr + s * 192;
    float* msb = g_ms + r * 128;
    float* mvb = g_mv + r * 576;
    const float i3 = rsqrtf(3.0f), i2 = rsqrtf(2.0f);

#pragma unroll 1
    for (int cg = 0; cg < 16; cg++) {
        const int c4 = cg * 4;
        float4 w1v = f4muls(gemv4(W4s, h, c4), 0.125f);
        float4 w2v = f4muls(gemv4(W4s, h, 64 + c4), 0.125f);
        float4 w3v = f4muls(gemv4(W4s, h, 128 + c4), 0.125f);
        float4 w4v = f4muls(gemv4(W4s, h, 192 + c4), 0.125f);
        float4 w5v = f4muls(gemv4(W4s, h, 256 + c4), 0.125f);

        float4 se = *(const float4*)(sb + c4);
        float4 vv[3];
        vv[0] = *(const float4*)(vb + c4);
        vv[1] = *(const float4*)(vb + 64 + c4);
        vv[2] = *(const float4*)(vb + 128 + c4);

        // scalar messages: p1 | p2
        red4v(msb + c4, f4muls(f4mul(w1v, se), sh0v));
        float4 dt = f4add(f4add(f4muls(vv[0], q[0]), f4muls(vv[1], q[1])),
                          f4muls(vv[2], q[2]));
        red4v(msb + 64 + c4, f4muls(f4mul(w2v, dt), i3));

        // vector messages: per path, 12 contiguous floats (4 ch x 3 xyz)
        float4 t3[3], t4[3], t5[3];
#pragma unroll
        for (int x = 0; x < 3; x++) {
            const int x1 = (x + 1) % 3, x2 = (x + 2) % 3;
            float4 cr = f4sub(f4muls(vv[x1], q[x2]), f4muls(vv[x2], q[x1]));
            t3[x] = f4muls(f4mul(w3v, se), q[x]);
            t4[x] = f4muls(f4mul(w4v, vv[x]), sh0v);
            t5[x] = f4muls(f4mul(w5v, cr), i2);
        }
        scatter12(mvb + 0 * 192 + c4 * 3, t3);
        scatter12(mvb + 1 * 192 + c4 * 3, t4);
        scatter12(mvb + 2 * 192 + c4 * 3, t5);
    }
}

// ===================== K3: output linear =====================
// smem floats: msm[192][68]@0 (13056) | wbuf[192][64]@13056 (12288)
#define K3_SMEM_BYTES (25344 * 4)
__global__ void __launch_bounds__(256) out_kernel(
    const float* __restrict__ Wouts, const float* __restrict__ Woutv,
    float* __restrict__ out) {
    extern __shared__ float sm[];
    float* msm = sm;
    float* wbuf = sm + 13056;
    const int tid = threadIdx.x;
    const int n0 = blockIdx.x * 64;
    const int tx = tid & 15, ty = tid >> 4;
    const int nb = ty * 4, db = tx * 4;
    float Y[4][4];

    for (int idx = tid; idx < 8192; idx += 256) {
        int n = idx >> 7, k = idx & 127, gn = n0 + n;
        msm[k * 68 + n] = (gn < NNODES) ? g_ms[gn * 128 + k] : 0.0f;
    }
    for (int idx = tid; idx < 8192; idx += 256) wbuf[idx] = Wouts[idx];
    __syncthreads();
    gemm_tile<128>(msm + nb, wbuf + db, Y);
    const float ss = rsqrtf(128.0f) / 16.0f;
#pragma unroll
    for (int i = 0; i < 4; i++) {
        int gn = n0 + nb + i;
        if (gn < NNODES)
            *(float4*)(out + gn * 64 + db) =
                make_float4(Y[i][0]*ss, Y[i][1]*ss, Y[i][2]*ss, Y[i][3]*ss);
    }
    __syncthreads();
    for (int idx = tid; idx < 12288; idx += 256) wbuf[idx] = Woutv[idx];
    const float sv = rsqrtf(192.0f) / 16.0f;
#pragma unroll 1
    for (int x = 0; x < 3; x++) {
        __syncthreads();
        for (int idx = tid; idx < 12288; idx += 256) {
            int n = idx / 192, k = idx - n * 192, gn = n0 + n;
            // g_mv layout: [n][3C][3] (x innermost)
            msm[k * 68 + n] = (gn < NNODES) ? g_mv[gn * 576 + k * 3 + x] : 0.0f;
        }
        __syncthreads();
        gemm_tile<192>(msm + nb, wbuf + db, Y);
#pragma unroll
        for (int i = 0; i < 4; i++) {
            int gn = n0 + nb + i;
            if (gn < NNODES)
#pragma unroll
                for (int j = 0; j < 4; j++)
                    out[OUT_V_OFF + gn * 192 + (db + j) * 3 + x] = Y[i][j] * sv;
        }
    }
}

// ===================== launch =====================
extern "C" void kernel_launch(void* const* d_in, const int* in_sizes, int n_in,
                              void* d_out, int out_size) {
    const float* attrs = (const float*)d_in[0];
    const float* fs    = (const float*)d_in[1];
    const float* fv    = (const float*)d_in[2];
    const float* sh0   = (const float*)d_in[3];
    const float* sh1   = (const float*)d_in[4];
    const float* ef    = (const float*)d_in[5];
    const int*   snd   = (const int*)d_in[6];
    const int*   rcv   = (const int*)d_in[7];
    const float* Wscs  = (const float*)d_in[8];
    const float* Wscv  = (const float*)d_in[9];
    const float* Wses  = (const float*)d_in[10];
    const float* Wsev  = (const float*)d_in[11];
    const float* W1    = (const float*)d_in[12];
    const float* W2    = (const float*)d_in[13];
    const float* W3    = (const float*)d_in[14];
    const float* W4    = (const float*)d_in[15];
    const float* Wouts = (const float*)d_in[16];
    const float* Woutv = (const float*)d_in[17];
    float* out = (float*)d_out;

    cudaFuncSetAttribute(node_kernel, cudaFuncAttributeMaxDynamicSharedMemorySize, K1_SMEM_BYTES);
    cudaFuncSetAttribute(edge_kernel, cudaFuncAttributeMaxDynamicSharedMemorySize, K2_SMEM_BYTES);
    cudaFuncSetAttribute(out_kernel,  cudaFuncAttributeMaxDynamicSharedMemorySize, K3_SMEM_BYTES);

    zero_kernel<<<1024, 256>>>();
    node_kernel<<<(NNODES + 63) / 64, 256, K1_SMEM_BYTES>>>(
        attrs, fs, fv, Wscs, Wscv, Wses, Wsev, out);
    edge_kernel<<<NEDGES / 256, 256, K2_SMEM_BYTES>>>(
        ef, sh0, sh1, snd, rcv, W1, W2, W3, W4);
    out_kernel<<<(NNODES + 63) / 64, 256, K3_SMEM_BYTES>>>(Wouts, Woutv, out);
}

// round 7
// speedup vs baseline: 1.4141x; 1.0537x over previous
#include <cuda_runtime.h>

#define NNODES 50000
#define NEDGES 320000
#define OUT_V_OFF 3200000
#define SC_S_OFF  12800000
#define SC_V_OFF  16000000

typedef unsigned long long u64;

// ---- scratch (__device__ globals: allocation-free) ----
__device__ float g_s_scr[NNODES * 64];
__device__ float g_v_scr[NNODES * 192];   // [n][x][c]
__device__ float g_ms[NNODES * 128];      // [n][2C]
__device__ float g_mv[NNODES * 576];      // [n][3C][3]  (x innermost)

__device__ __forceinline__ float silu_f(float x) { return x / (1.0f + __expf(-x)); }

// ---- packed fp32x2 primitives (SASS FFMA2 path; exact fp32) ----
__device__ __forceinline__ u64 pack2(float lo, float hi) {
    u64 r; asm("mov.b64 %0, {%1, %2};" : "=l"(r) : "f"(lo), "f"(hi)); return r;
}
__device__ __forceinline__ u64 fma2(u64 a, u64 b, u64 c) {
    u64 d; asm("fma.rn.f32x2 %0, %1, %2, %3;" : "=l"(d) : "l"(a), "l"(b), "l"(c)); return d;
}
__device__ __forceinline__ void unpack2(u64 v, float& lo, float& hi) {
    asm("mov.b64 {%0, %1}, %2;" : "=f"(lo), "=f"(hi) : "l"(v));
}

// vectorized f32 reduction (sm_90+): one 16B L2 atomic op
__device__ __forceinline__ void red4v(float* p, float4 v) {
    asm volatile("red.global.add.v4.f32 [%0], {%1, %2, %3, %4};"
                 :: "l"(p), "f"(v.x), "f"(v.y), "f"(v.z), "f"(v.w) : "memory");
}

__device__ __forceinline__ float4 f4mul(float4 a, float4 b) {
    return make_float4(a.x*b.x, a.y*b.y, a.z*b.z, a.w*b.w);
}
__device__ __forceinline__ float4 f4muls(float4 a, float s) {
    return make_float4(a.x*s, a.y*s, a.z*s, a.w*s);
}
__device__ __forceinline__ float4 f4sub(float4 a, float4 b) {
    return make_float4(a.x-b.x, a.y-b.y, a.z-b.z, a.w-b.w);
}
__device__ __forceinline__ float4 f4add(float4 a, float4 b) {
    return make_float4(a.x+b.x, a.y+b.y, a.z+b.z, a.w+b.w);
}

// scatter 12 contiguous floats (4 channels x 3 xyz, x innermost) as 3 v4 reds.
__device__ __forceinline__ void scatter12(float* p, const float4 t[3]) {
    red4v(p + 0, make_float4(t[0].x, t[1].x, t[2].x, t[0].y));
    red4v(p + 4, make_float4(t[1].y, t[2].y, t[0].z, t[1].z));
    red4v(p + 8, make_float4(t[2].z, t[0].w, t[1].w, t[2].w));
}

// 4-node x 4-d register-tile GEMM using FFMA2.
// A: [K][68] node-contig padded (row pairs packed naturally), W: [K][64].
// Y2[ip][j]: ip = node-pair (rows 2ip,2ip+1 in lo,hi), j = 4 d-columns.
template <int K>
__device__ __forceinline__ void gemm_tile2(const float* __restrict__ A,
                                           const float* __restrict__ W,
                                           u64 Y2[2][4]) {
#pragma unroll
    for (int ip = 0; ip < 2; ip++)
#pragma unroll
        for (int j = 0; j < 4; j++) Y2[ip][j] = 0ull;
#pragma unroll 8
    for (int c = 0; c < K; c++) {
        ulonglong2 a2 = *(const ulonglong2*)(A + c * 68);
        float4 w = *(const float4*)(W + c * 64);
        u64 w0 = pack2(w.x, w.x), w1 = pack2(w.y, w.y);
        u64 w2 = pack2(w.z, w.z), w3 = pack2(w.w, w.w);
        Y2[0][0] = fma2(a2.x, w0, Y2[0][0]);
        Y2[0][1] = fma2(a2.x, w1, Y2[0][1]);
        Y2[0][2] = fma2(a2.x, w2, Y2[0][2]);
        Y2[0][3] = fma2(a2.x, w3, Y2[0][3]);
        Y2[1][0] = fma2(a2.y, w0, Y2[1][0]);
        Y2[1][1] = fma2(a2.y, w1, Y2[1][1]);
        Y2[1][2] = fma2(a2.y, w2, Y2[1][2]);
        Y2[1][3] = fma2(a2.y, w3, Y2[1][3]);
    }
}

// ===================== K0: zero scratch =====================
__global__ void zero_kernel() {
    long i = (long)blockIdx.x * blockDim.x + threadIdx.x;
    long t = (long)gridDim.x * blockDim.x;
    float4 z = make_float4(0.f, 0.f, 0.f, 0.f);
    for (long j = i; j < (long)NNODES * 128 / 4; j += t) ((float4*)g_ms)[j] = z;
    for (long j = i; j < (long)NNODES * 576 / 4; j += t) ((float4*)g_mv)[j] = z;
}

// ===================== K1: node side =====================
// smem floats: fsm[64][68]@0 | fvm[3][64][68]@4352 | wbuf[64][64]@17408 | attr[64][10]@21504
#define K1_SMEM_BYTES (22144 * 4)
__global__ void __launch_bounds__(256) node_kernel(
    const float* __restrict__ attrs_g, const float* __restrict__ fs_g,
    const float* __restrict__ fv_g,
    const float* __restrict__ Wscs, const float* __restrict__ Wscv,
    const float* __restrict__ Wses, const float* __restrict__ Wsev,
    float* __restrict__ out) {
    extern __shared__ float sm[];
    float* fsm = sm;
    float* fvm = sm + 4352;
    float* wbuf = sm + 17408;
    float* atm = sm + 21504;
    const int tid = threadIdx.x;
    const int n0 = blockIdx.x * 64;

    for (int idx = tid; idx < 4096; idx += 256) {
        int n = idx >> 6, c = idx & 63, gn = n0 + n;
        fsm[c * 68 + n] = (gn < NNODES) ? fs_g[gn * 64 + c] : 0.0f;
    }
    for (int idx = tid; idx < 12288; idx += 256) {
        int n = idx / 192, r = idx - n * 192, c = r / 3, x = r - c * 3, gn = n0 + n;
        fvm[x * 4352 + c * 68 + n] = (gn < NNODES) ? fv_g[gn * 192 + c * 3 + x] : 0.0f;
    }
    for (int idx = tid; idx < 640; idx += 256) {
        int n = idx / 10, gn = n0 + n;
        atm[idx] = (gn < NNODES) ? attrs_g[gn * 10 + (idx - n * 10)] : 0.0f;
    }

    const int tx = tid & 15, ty = tid >> 4;
    const int nb = ty * 4, db = tx * 4;
    u64 acc_s[2][4], acc_v[3][2][4], Y2[2][4];
#pragma unroll
    for (int ip = 0; ip < 2; ip++)
#pragma unroll
        for (int j = 0; j < 4; j++) acc_s[ip][j] = 0ull;
#pragma unroll
    for (int x = 0; x < 3; x++)
#pragma unroll
        for (int ip = 0; ip < 2; ip++)
#pragma unroll
            for (int j = 0; j < 4; j++) acc_v[x][ip][j] = 0ull;

    // scalar skip-TP: 10 attr passes
    for (int a = 0; a < 10; a++) {
        __syncthreads();
        for (int idx = tid; idx < 4096; idx += 256)
            wbuf[idx] = Wscs[((idx >> 6) * 10 + a) * 64 + (idx & 63)];
        __syncthreads();
        gemm_tile2<64>(fsm + nb, wbuf + db, Y2);
#pragma unroll
        for (int ip = 0; ip < 2; ip++) {
            u64 av2 = pack2(atm[(nb + 2*ip) * 10 + a], atm[(nb + 2*ip + 1) * 10 + a]);
#pragma unroll
            for (int j = 0; j < 4; j++) acc_s[ip][j] = fma2(av2, Y2[ip][j], acc_s[ip][j]);
        }
    }
    // vector skip-TP: 10 attr passes x 3 components
    for (int a = 0; a < 10; a++) {
        __syncthreads();
        for (int idx = tid; idx < 4096; idx += 256)
            wbuf[idx] = Wscv[((idx >> 6) * 10 + a) * 64 + (idx & 63)];
        __syncthreads();
#pragma unroll 1
        for (int x = 0; x < 3; x++) {
            gemm_tile2<64>(fvm + x * 4352 + nb, wbuf + db, Y2);
#pragma unroll
            for (int ip = 0; ip < 2; ip++) {
                u64 av2 = pack2(atm[(nb + 2*ip) * 10 + a], atm[(nb + 2*ip + 1) * 10 + a]);
#pragma unroll
                for (int j = 0; j < 4; j++) acc_v[x][ip][j] = fma2(av2, Y2[ip][j], acc_v[x][ip][j]);
            }
        }
    }
    // self linear (scalar)
    __syncthreads();
    for (int idx = tid; idx < 4096; idx += 256) wbuf[idx] = Wses[idx];
    __syncthreads();
    gemm_tile2<64>(fsm + nb, wbuf + db, Y2);
#pragma unroll
    for (int ip = 0; ip < 2; ip++) {
        float y[2][4];
#pragma unroll
        for (int j = 0; j < 4; j++) unpack2(Y2[ip][j], y[0][j], y[1][j]);
#pragma unroll
        for (int h = 0; h < 2; h++) {
            int gn = n0 + nb + 2*ip + h;
            if (gn < NNODES)
                *(float4*)(g_s_scr + gn * 64 + db) =
                    make_float4(y[h][0]*0.125f, y[h][1]*0.125f, y[h][2]*0.125f, y[h][3]*0.125f);
        }
    }
    // self linear (vector)
    __syncthreads();
    for (int idx = tid; idx < 4096; idx += 256) wbuf[idx] = Wsev[idx];
    __syncthreads();
#pragma unroll 1
    for (int x = 0; x < 3; x++) {
        gemm_tile2<64>(fvm + x * 4352 + nb, wbuf + db, Y2);
#pragma unroll
        for (int ip = 0; ip < 2; ip++) {
            float y[2][4];
#pragma unroll
            for (int j = 0; j < 4; j++) unpack2(Y2[ip][j], y[0][j], y[1][j]);
#pragma unroll
            for (int h = 0; h < 2; h++) {
                int gn = n0 + nb + 2*ip + h;
                if (gn < NNODES)
                    *(float4*)(g_v_scr + gn * 192 + x * 64 + db) =
                        make_float4(y[h][0]*0.125f, y[h][1]*0.125f, y[h][2]*0.125f, y[h][3]*0.125f);
            }
        }
    }
    // skip-connection outputs
    const float isc = rsqrtf(640.0f);
#pragma unroll
    for (int ip = 0; ip < 2; ip++) {
        float ys[2][4], yv[3][2][4];
#pragma unroll
        for (int j = 0; j < 4; j++) {
            unpack2(acc_s[ip][j], ys[0][j], ys[1][j]);
#pragma unroll
            for (int x = 0; x < 3; x++) unpack2(acc_v[x][ip][j], yv[x][0][j], yv[x][1][j]);
        }
#pragma unroll
        for (int h = 0; h < 2; h++) {
            int gn = n0 + nb + 2*ip + h;
            if (gn < NNODES) {
                *(float4*)(out + SC_S_OFF + gn * 64 + db) =
                    make_float4(ys[h][0]*isc, ys[h][1]*isc, ys[h][2]*isc, ys[h][3]*isc);
#pragma unroll
                for (int j = 0; j < 4; j++)
#pragma unroll
                    for (int x = 0; x < 3; x++)
                        out[SC_V_OFF + (gn * 64 + db + j) * 3 + x] = yv[x][h][j] * isc;
            }
        }
    }
}

// ===================== K2: edge side =====================
// smem floats: W1s@0(512) W2s@512(4096) W3s@4608(4096) W4s@8704(20480) hsm@29184(16384)
#define K2_SMEM_BYTES (45568 * 4)

// 64->64 MLP layer with FFMA2; hd = packed-duplicated activations.
__device__ __forceinline__ void mlp_layer2(const float* __restrict__ Wsm,
                                           const u64 hd[64],
                                           float* __restrict__ hsm, int tid,
                                           float scale) {
#pragma unroll 1
    for (int dg = 0; dg < 16; dg++) {
        u64 a0 = 0ull, a1 = 0ull;
#pragma unroll
        for (int c = 0; c < 64; c++) {
            ulonglong2 w2 = *(const ulonglong2*)(Wsm + c * 64 + dg * 4);
            a0 = fma2(hd[c], w2.x, a0);
            a1 = fma2(hd[c], w2.y, a1);
        }
        float v0, v1, v2, v3;
        unpack2(a0, v0, v1); unpack2(a1, v2, v3);
        hsm[(dg*4+0)*256+tid] = silu_f(v0*scale);
        hsm[(dg*4+1)*256+tid] = silu_f(v1*scale);
        hsm[(dg*4+2)*256+tid] = silu_f(v2*scale);
        hsm[(dg*4+3)*256+tid] = silu_f(v3*scale);
    }
}

// 4-wide GEMV column group via FFMA2.
__device__ __forceinline__ float4 gemv2(const float* __restrict__ W4s,
                                        const u64 hd[64], int col) {
    u64 r0 = 0ull, r1 = 0ull;
#pragma unroll
    for (int k = 0; k < 64; k++) {
        ulonglong2 t = *(const ulonglong2*)(W4s + k * 320 + col);
        r0 = fma2(hd[k], t.x, r0);
        r1 = fma2(hd[k], t.y, r1);
    }
    float4 o;
    unpack2(r0, o.x, o.y); unpack2(r1, o.z, o.w);
    return o;
}

__global__ void __launch_bounds__(256) edge_kernel(
    const float* __restrict__ ef_g, const float* __restrict__ sh0_g,
    const float* __restrict__ sh1_g, const int* __restrict__ snd_g,
    const int* __restrict__ rcv_g,
    const float* __restrict__ W1, const float* __restrict__ W2,
    const float* __restrict__ W3, const float* __restrict__ W4) {
    extern __shared__ float sm[];
    float* W1s = sm;
    float* W2s = sm + 512;
    float* W3s = sm + 4608;
    float* W4s = sm + 8704;
    float* hsm = sm + 29184;
    const int tid = threadIdx.x;

    for (int i = tid; i < 512; i += 256) W1s[i] = W1[i];
    for (int i = tid; i < 4096; i += 256) W2s[i] = W2[i];
    for (int i = tid; i < 4096; i += 256) W3s[i] = W3[i];
    for (int i = tid; i < 20480; i += 256) W4s[i] = W4[i];
    __syncthreads();

    const int e = blockIdx.x * 256 + tid;  // E divisible by 256
    float efr[8];
    {
        float4 t0 = *(const float4*)(ef_g + e * 8);
        float4 t1 = *(const float4*)(ef_g + e * 8 + 4);
        efr[0]=t0.x; efr[1]=t0.y; efr[2]=t0.z; efr[3]=t0.w;
        efr[4]=t1.x; efr[5]=t1.y; efr[6]=t1.z; efr[7]=t1.w;
    }
    // layer 1 (8 -> 64), scalar FFMA (small)
    const float invs8 = rsqrtf(8.0f);
#pragma unroll 1
    for (int dg = 0; dg < 16; dg++) {
        float4 acc = make_float4(0.f, 0.f, 0.f, 0.f);
#pragma unroll
        for (int j = 0; j < 8; j++) {
            float4 w = *(const float4*)(W1s + j * 64 + dg * 4);
            float ej = efr[j];
            acc.x += ej*w.x; acc.y += ej*w.y; acc.z += ej*w.z; acc.w += ej*w.w;
        }
        hsm[(dg*4+0)*256+tid] = silu_f(acc.x*invs8);
        hsm[(dg*4+1)*256+tid] = silu_f(acc.y*invs8);
        hsm[(dg*4+2)*256+tid] = silu_f(acc.z*invs8);
        hsm[(dg*4+3)*256+tid] = silu_f(acc.w*invs8);
    }
    u64 hd[64];
#pragma unroll
    for (int c = 0; c < 64; c++) { float v = hsm[c * 256 + tid]; hd[c] = pack2(v, v); }
    mlp_layer2(W2s, hd, hsm, tid, 0.125f);
#pragma unroll
    for (int c = 0; c < 64; c++) { float v = hsm[c * 256 + tid]; hd[c] = pack2(v, v); }
    mlp_layer2(W3s, hd, hsm, tid, 0.125f);
#pragma unroll
    for (int c = 0; c < 64; c++) { float v = hsm[c * 256 + tid]; hd[c] = pack2(v, v); }

    const int s = snd_g[e];
    const int r = rcv_g[e];
    const float sh0v = sh0_g[e];
    float q[3];
    q[0] = sh1_g[e*3+0]; q[1] = sh1_g[e*3+1]; q[2] = sh1_g[e*3+2];
    const float* sb = g_s_scr + s * 64;
    const float* vb = g_v_scr + s * 192;
    float* msb = g_ms + r * 128;
    float* mvb = g_mv + r * 576;
    const float i3 = rsqrtf(3.0f), i2 = rsqrtf(2.0f);

#pragma unroll 1
    for (int cg = 0; cg < 16; cg++) {
        const int c4 = cg * 4;
        float4 w1v = f4muls(gemv2(W4s, hd, c4), 0.125f);
        float4 w2v = f4muls(gemv2(W4s, hd, 64 + c4), 0.125f);
        float4 w3v = f4muls(gemv2(W4s, hd, 128 + c4), 0.125f);
        float4 w4v = f4muls(gemv2(W4s, hd, 192 + c4), 0.125f);
        float4 w5v = f4muls(gemv2(W4s, hd, 256 + c4), 0.125f);

        float4 se = *(const float4*)(sb + c4);
        float4 vv[3];
        vv[0] = *(const float4*)(vb + c4);
        vv[1] = *(const float4*)(vb + 64 + c4);
        vv[2] = *(const float4*)(vb + 128 + c4);

        // scalar messages: p1 | p2
        red4v(msb + c4, f4muls(f4mul(w1v, se), sh0v));
        float4 dt = f4add(f4add(f4muls(vv[0], q[0]), f4muls(vv[1], q[1])),
                          f4muls(vv[2], q[2]));
        red4v(msb + 64 + c4, f4muls(f4mul(w2v, dt), i3));

        // vector messages: per path, 12 contiguous floats (4 ch x 3 xyz)
        float4 t3[3], t4[3], t5[3];
#pragma unroll
        for (int x = 0; x < 3; x++) {
            const int x1 = (x + 1) % 3, x2 = (x + 2) % 3;
            float4 cr = f4sub(f4muls(vv[x1], q[x2]), f4muls(vv[x2], q[x1]));
            t3[x] = f4muls(f4mul(w3v, se), q[x]);
            t4[x] = f4muls(f4mul(w4v, vv[x]), sh0v);
            t5[x] = f4muls(f4mul(w5v, cr), i2);
        }
        scatter12(mvb + 0 * 192 + c4 * 3, t3);
        scatter12(mvb + 1 * 192 + c4 * 3, t4);
        scatter12(mvb + 2 * 192 + c4 * 3, t5);
    }
}

// ===================== K3: output linear =====================
// smem floats: msm[192][68]@0 (13056) | wbuf[192][64]@13056 (12288)
#define K3_SMEM_BYTES (25344 * 4)
__global__ void __launch_bounds__(256) out_kernel(
    const float* __restrict__ Wouts, const float* __restrict__ Woutv,
    float* __restrict__ out) {
    extern __shared__ float sm[];
    float* msm = sm;
    float* wbuf = sm + 13056;
    const int tid = threadIdx.x;
    const int n0 = blockIdx.x * 64;
    const int tx = tid & 15, ty = tid >> 4;
    const int nb = ty * 4, db = tx * 4;
    u64 Y2[2][4];

    for (int idx = tid; idx < 8192; idx += 256) {
        int n = idx >> 7, k = idx & 127, gn = n0 + n;
        msm[k * 68 + n] = (gn < NNODES) ? g_ms[gn * 128 + k] : 0.0f;
    }
    for (int idx = tid; idx < 8192; idx += 256) wbuf[idx] = Wouts[idx];
    __syncthreads();
    gemm_tile2<128>(msm + nb, wbuf + db, Y2);
    const float ss = rsqrtf(128.0f) / 16.0f;
#pragma unroll
    for (int ip = 0; ip < 2; ip++) {
        float y[2][4];
#pragma unroll
        for (int j = 0; j < 4; j++) unpack2(Y2[ip][j], y[0][j], y[1][j]);
#pragma unroll
        for (int h = 0; h < 2; h++) {
            int gn = n0 + nb + 2*ip + h;
            if (gn < NNODES)
                *(float4*)(out + gn * 64 + db) =
                    make_float4(y[h][0]*ss, y[h][1]*ss, y[h][2]*ss, y[h][3]*ss);
        }
    }
    __syncthreads();
    for (int idx = tid; idx < 12288; idx += 256) wbuf[idx] = Woutv[idx];
    const float sv = rsqrtf(192.0f) / 16.0f;
#pragma unroll 1
    for (int x = 0; x < 3; x++) {
        __syncthreads();
        for (int idx = tid; idx < 12288; idx += 256) {
            int n = idx / 192, k = idx - n * 192, gn = n0 + n;
            msm[k * 68 + n] = (gn < NNODES) ? g_mv[gn * 576 + k * 3 + x] : 0.0f;
        }
        __syncthreads();
        gemm_tile2<192>(msm + nb, wbuf + db, Y2);
#pragma unroll
        for (int ip = 0; ip < 2; ip++) {
            float y[2][4];
#pragma unroll
            for (int j = 0; j < 4; j++) unpack2(Y2[ip][j], y[0][j], y[1][j]);
#pragma unroll
            for (int h = 0; h < 2; h++) {
                int gn = n0 + nb + 2*ip + h;
                if (gn < NNODES)
#pragma unroll
                    for (int j = 0; j < 4; j++)
                        out[OUT_V_OFF + gn * 192 + (db + j) * 3 + x] = y[h][j] * sv;
            }
        }
    }
}

// ===================== launch =====================
extern "C" void kernel_launch(void* const* d_in, const int* in_sizes, int n_in,
                              void* d_out, int out_size) {
    const float* attrs = (const float*)d_in[0];
    const float* fs    = (const float*)d_in[1];
    const float* fv    = (const float*)d_in[2];
    const float* sh0   = (const float*)d_in[3];
    const float* sh1   = (const float*)d_in[4];
    const float* ef    = (const float*)d_in[5];
    const int*   snd   = (const int*)d_in[6];
    const int*   rcv   = (const int*)d_in[7];
    const float* Wscs  = (const float*)d_in[8];
    const float* Wscv  = (const float*)d_in[9];
    const float* Wses  = (const float*)d_in[10];
    const float* Wsev  = (const float*)d_in[11];
    const float* W1    = (const float*)d_in[12];
    const float* W2    = (const float*)d_in[13];
    const float* W3    = (const float*)d_in[14];
    const float* W4    = (const float*)d_in[15];
    const float* Wouts = (const float*)d_in[16];
    const float* Woutv = (const float*)d_in[17];
    float* out = (float*)d_out;

    cudaFuncSetAttribute(node_kernel, cudaFuncAttributeMaxDynamicSharedMemorySize, K1_SMEM_BYTES);
    cudaFuncSetAttribute(edge_kernel, cudaFuncAttributeMaxDynamicSharedMemorySize, K2_SMEM_BYTES);
    cudaFuncSetAttribute(out_kernel,  cudaFuncAttributeMaxDynamicSharedMemorySize, K3_SMEM_BYTES);

    zero_kernel<<<1024, 256>>>();
    node_kernel<<<(NNODES + 63) / 64, 256, K1_SMEM_BYTES>>>(
        attrs, fs, fv, Wscs, Wscv, Wses, Wsev, out);
    edge_kernel<<<NEDGES / 256, 256, K2_SMEM_BYTES>>>(
        ef, sh0, sh1, snd, rcv, W1, W2, W3, W4);
    out_kernel<<<(NNODES + 63) / 64, 256, K3_SMEM_BYTES>>>(Wouts, Woutv, out);
}

// round 9
// speedup vs baseline: 1.5257x; 1.0789x over previous
#include <cuda_runtime.h>

#define NNODES 50000
#define NEDGES 320000
#define OUT_V_OFF 3200000
#define SC_S_OFF  12800000
#define SC_V_OFF  16000000

typedef unsigned long long u64;

// ---- scratch (__device__ globals: allocation-free) ----
__device__ float g_s_scr[NNODES * 64];
__device__ float g_v_scr[NNODES * 192];   // [n][x][c]
__device__ float g_ms[NNODES * 128];      // [n][2C]
__device__ float g_mv[NNODES * 576];      // [n][3C][3]  (x innermost)

__device__ __forceinline__ float silu_f(float x) { return x / (1.0f + __expf(-x)); }

// ---- packed fp32x2 primitives ----
__device__ __forceinline__ u64 pack2(float lo, float hi) {
    u64 r; asm("mov.b64 %0, {%1, %2};" : "=l"(r) : "f"(lo), "f"(hi)); return r;
}
__device__ __forceinline__ u64 fma2(u64 a, u64 b, u64 c) {
    u64 d; asm("fma.rn.f32x2 %0, %1, %2, %3;" : "=l"(d) : "l"(a), "l"(b), "l"(c)); return d;
}
__device__ __forceinline__ void unpack2(u64 v, float& lo, float& hi) {
    asm("mov.b64 {%0, %1}, %2;" : "=f"(lo), "=f"(hi) : "l"(v));
}

// vectorized f32 reduction (sm_90+): one 16B L2 atomic op
__device__ __forceinline__ void red4v(float* p, float4 v) {
    asm volatile("red.global.add.v4.f32 [%0], {%1, %2, %3, %4};"
                 :: "l"(p), "f"(v.x), "f"(v.y), "f"(v.z), "f"(v.w) : "memory");
}

__device__ __forceinline__ float4 f4mul(float4 a, float4 b) {
    return make_float4(a.x*b.x, a.y*b.y, a.z*b.z, a.w*b.w);
}
__device__ __forceinline__ float4 f4muls(float4 a, float s) {
    return make_float4(a.x*s, a.y*s, a.z*s, a.w*s);
}
__device__ __forceinline__ float4 f4sub(float4 a, float4 b) {
    return make_float4(a.x-b.x, a.y-b.y, a.z-b.z, a.w-b.w);
}
__device__ __forceinline__ float4 f4add(float4 a, float4 b) {
    return make_float4(a.x+b.x, a.y+b.y, a.z+b.z, a.w+b.w);
}

// interleaved vector-path scatter: 12 contiguous floats [4ch x 3xyz] = 3 v4 reds.
__device__ __forceinline__ void scatter_vec_group(float* dst, float4 val,
                                                  float4 ax, float4 ay, float4 az) {
    red4v(dst + 0, make_float4(val.x*ax.x, val.x*ay.x, val.x*az.x, val.y*ax.y));
    red4v(dst + 4, make_float4(val.y*ay.y, val.y*az.y, val.z*ax.z, val.z*ay.z));
    red4v(dst + 8, make_float4(val.z*az.z, val.w*ax.w, val.w*ay.w, val.w*az.w));
}

// 4-row x 4-col register-tile GEMM using packed fp32x2.
// A: [K][68] row(edge/node)-contig padded, W: [K][64].
template <int K>
__device__ __forceinline__ void gemm_tile2(const float* __restrict__ A,
                                           const float* __restrict__ W,
                                           u64 Y2[2][4]) {
#pragma unroll
    for (int ip = 0; ip < 2; ip++)
#pragma unroll
        for (int j = 0; j < 4; j++) Y2[ip][j] = 0ull;
#pragma unroll 8
    for (int c = 0; c < K; c++) {
        ulonglong2 a2 = *(const ulonglong2*)(A + c * 68);
        float4 w = *(const float4*)(W + c * 64);
        u64 w0 = pack2(w.x, w.x), w1 = pack2(w.y, w.y);
        u64 w2 = pack2(w.z, w.z), w3 = pack2(w.w, w.w);
        Y2[0][0] = fma2(a2.x, w0, Y2[0][0]);
        Y2[0][1] = fma2(a2.x, w1, Y2[0][1]);
        Y2[0][2] = fma2(a2.x, w2, Y2[0][2]);
        Y2[0][3] = fma2(a2.x, w3, Y2[0][3]);
        Y2[1][0] = fma2(a2.y, w0, Y2[1][0]);
        Y2[1][1] = fma2(a2.y, w1, Y2[1][1]);
        Y2[1][2] = fma2(a2.y, w2, Y2[1][2]);
        Y2[1][3] = fma2(a2.y, w3, Y2[1][3]);
    }
}

// ===================== K0: zero scratch =====================
__global__ void zero_kernel() {
    long i = (long)blockIdx.x * blockDim.x + threadIdx.x;
    long t = (long)gridDim.x * blockDim.x;
    float4 z = make_float4(0.f, 0.f, 0.f, 0.f);
    for (long j = i; j < (long)NNODES * 128 / 4; j += t) ((float4*)g_ms)[j] = z;
    for (long j = i; j < (long)NNODES * 576 / 4; j += t) ((float4*)g_mv)[j] = z;
}

// ===================== K1: node side (unchanged, passing since R5) ==========
#define K1_SMEM_BYTES (22144 * 4)
__global__ void __launch_bounds__(256) node_kernel(
    const float* __restrict__ attrs_g, const float* __restrict__ fs_g,
    const float* __restrict__ fv_g,
    const float* __restrict__ Wscs, const float* __restrict__ Wscv,
    const float* __restrict__ Wses, const float* __restrict__ Wsev,
    float* __restrict__ out) {
    extern __shared__ float sm[];
    float* fsm = sm;
    float* fvm = sm + 4352;
    float* wbuf = sm + 17408;
    float* atm = sm + 21504;
    const int tid = threadIdx.x;
    const int n0 = blockIdx.x * 64;

    for (int idx = tid; idx < 4096; idx += 256) {
        int n = idx >> 6, c = idx & 63, gn = n0 + n;
        fsm[c * 68 + n] = (gn < NNODES) ? fs_g[gn * 64 + c] : 0.0f;
    }
    for (int idx = tid; idx < 12288; idx += 256) {
        int n = idx / 192, r = idx - n * 192, c = r / 3, x = r - c * 3, gn = n0 + n;
        fvm[x * 4352 + c * 68 + n] = (gn < NNODES) ? fv_g[gn * 192 + c * 3 + x] : 0.0f;
    }
    for (int idx = tid; idx < 640; idx += 256) {
        int n = idx / 10, gn = n0 + n;
        atm[idx] = (gn < NNODES) ? attrs_g[gn * 10 + (idx - n * 10)] : 0.0f;
    }

    const int tx = tid & 15, ty = tid >> 4;
    const int nb = ty * 4, db = tx * 4;
    u64 acc_s[2][4], acc_v[3][2][4], Y2[2][4];
#pragma unroll
    for (int ip = 0; ip < 2; ip++)
#pragma unroll
        for (int j = 0; j < 4; j++) acc_s[ip][j] = 0ull;
#pragma unroll
    for (int x = 0; x < 3; x++)
#pragma unroll
        for (int ip = 0; ip < 2; ip++)
#pragma unroll
            for (int j = 0; j < 4; j++) acc_v[x][ip][j] = 0ull;

    for (int a = 0; a < 10; a++) {
        __syncthreads();
        for (int idx = tid; idx < 4096; idx += 256)
            wbuf[idx] = Wscs[((idx >> 6) * 10 + a) * 64 + (idx & 63)];
        __syncthreads();
        gemm_tile2<64>(fsm + nb, wbuf + db, Y2);
#pragma unroll
        for (int ip = 0; ip < 2; ip++) {
            u64 av2 = pack2(atm[(nb + 2*ip) * 10 + a], atm[(nb + 2*ip + 1) * 10 + a]);
#pragma unroll
            for (int j = 0; j < 4; j++) acc_s[ip][j] = fma2(av2, Y2[ip][j], acc_s[ip][j]);
        }
    }
    for (int a = 0; a < 10; a++) {
        __syncthreads();
        for (int idx = tid; idx < 4096; idx += 256)
            wbuf[idx] = Wscv[((idx >> 6) * 10 + a) * 64 + (idx & 63)];
        __syncthreads();
#pragma unroll 1
        for (int x = 0; x < 3; x++) {
            gemm_tile2<64>(fvm + x * 4352 + nb, wbuf + db, Y2);
#pragma unroll
            for (int ip = 0; ip < 2; ip++) {
                u64 av2 = pack2(atm[(nb + 2*ip) * 10 + a], atm[(nb + 2*ip + 1) * 10 + a]);
#pragma unroll
                for (int j = 0; j < 4; j++) acc_v[x][ip][j] = fma2(av2, Y2[ip][j], acc_v[x][ip][j]);
            }
        }
    }
    __syncthreads();
    for (int idx = tid; idx < 4096; idx += 256) wbuf[idx] = Wses[idx];
    __syncthreads();
    gemm_tile2<64>(fsm + nb, wbuf + db, Y2);
#pragma unroll
    for (int ip = 0; ip < 2; ip++) {
        float y[2][4];
#pragma unroll
        for (int j = 0; j < 4; j++) unpack2(Y2[ip][j], y[0][j], y[1][j]);
#pragma unroll
        for (int h = 0; h < 2; h++) {
            int gn = n0 + nb + 2*ip + h;
            if (gn < NNODES)
                *(float4*)(g_s_scr + gn * 64 + db) =
                    make_float4(y[h][0]*0.125f, y[h][1]*0.125f, y[h][2]*0.125f, y[h][3]*0.125f);
        }
    }
    __syncthreads();
    for (int idx = tid; idx < 4096; idx += 256) wbuf[idx] = Wsev[idx];
    __syncthreads();
#pragma unroll 1
    for (int x = 0; x < 3; x++) {
        gemm_tile2<64>(fvm + x * 4352 + nb, wbuf + db, Y2);
#pragma unroll
        for (int ip = 0; ip < 2; ip++) {
            float y[2][4];
#pragma unroll
            for (int j = 0; j < 4; j++) unpack2(Y2[ip][j], y[0][j], y[1][j]);
#pragma unroll
            for (int h = 0; h < 2; h++) {
                int gn = n0 + nb + 2*ip + h;
                if (gn < NNODES)
                    *(float4*)(g_v_scr + gn * 192 + x * 64 + db) =
                        make_float4(y[h][0]*0.125f, y[h][1]*0.125f, y[h][2]*0.125f, y[h][3]*0.125f);
            }
        }
    }
    const float isc = rsqrtf(640.0f);
#pragma unroll
    for (int ip = 0; ip < 2; ip++) {
        float ys[2][4], yv[3][2][4];
#pragma unroll
        for (int j = 0; j < 4; j++) {
            unpack2(acc_s[ip][j], ys[0][j], ys[1][j]);
#pragma unroll
            for (int x = 0; x < 3; x++) unpack2(acc_v[x][ip][j], yv[x][0][j], yv[x][1][j]);
        }
#pragma unroll
        for (int h = 0; h < 2; h++) {
            int gn = n0 + nb + 2*ip + h;
            if (gn < NNODES) {
                *(float4*)(out + SC_S_OFF + gn * 64 + db) =
                    make_float4(ys[h][0]*isc, ys[h][1]*isc, ys[h][2]*isc, ys[h][3]*isc);
#pragma unroll
                for (int j = 0; j < 4; j++)
#pragma unroll
                    for (int x = 0; x < 3; x++)
                        out[SC_V_OFF + (gn * 64 + db + j) * 3 + x] = yv[x][h][j] * isc;
            }
        }
    }
}

// ===================== K2: edge side, block-cooperative GEMM =====================
// Tile = 64 edges / CTA (256 threads). smem (floats):
//   A   @0      (4352)  act buffer (k-major [64][68])
//   B   @4352   (4352)  act buffer
//   WB  @8704   (4096)  staged weights [K][64]
//   WSM @12800  (4352)  path weights, edge-major [64][68]
//   META@17152  (384)   s,r (int), sh0, qx, qy, qz
#define EA   0
#define EB   4352
#define EWB  8704
#define EWSM 12800
#define EMETA 17152
#define K2_SMEM_BYTES (17536 * 4)

// transposed (k-major) activation store with silu
__device__ __forceinline__ void store_actT(float* dst, const u64 Y2[2][4],
                                           int nb, int db, float scale) {
#pragma unroll
    for (int ip = 0; ip < 2; ip++)
#pragma unroll
        for (int j = 0; j < 4; j++) {
            float lo, hi; unpack2(Y2[ip][j], lo, hi);
            dst[(db + j) * 68 + nb + 2*ip]     = silu_f(lo * scale);
            dst[(db + j) * 68 + nb + 2*ip + 1] = silu_f(hi * scale);
        }
}

__global__ void __launch_bounds__(256) edge_kernel(
    const float* __restrict__ ef_g, const float* __restrict__ sh0_g,
    const float* __restrict__ sh1_g, const int* __restrict__ snd_g,
    const int* __restrict__ rcv_g,
    const float* __restrict__ W1, const float* __restrict__ W2,
    const float* __restrict__ W3, const float* __restrict__ W4) {
    extern __shared__ float sm[];
    const int tid = threadIdx.x;
    const int e0 = blockIdx.x * 64;
    const int tx = tid & 15, ty = tid >> 4;
    const int nb = ty * 4, db = tx * 4;
    u64 Y2[2][4];

    // ---- stage edge tile metadata + features ----
    if (tid < 64) {
        int ge = e0 + tid;
        ((int*)(sm + EMETA))[tid]      = snd_g[ge];
        ((int*)(sm + EMETA + 64))[tid] = rcv_g[ge];
        sm[EMETA + 128 + tid] = sh0_g[ge];
        sm[EMETA + 192 + tid] = sh1_g[ge * 3 + 0];
        sm[EMETA + 256 + tid] = sh1_g[ge * 3 + 1];
        sm[EMETA + 320 + tid] = sh1_g[ge * 3 + 2];
    }
    // ef k-major: A[k][e]  (512 items, 256 threads -> strided loop!)
    for (int i = tid; i < 512; i += 256) {
        int e = i >> 3, k = i & 7;
        sm[EA + k * 68 + e] = ef_g[(e0 + e) * 8 + k];
    }
    // stage W1 [8][64]  (512 items, strided loop)
    for (int i = tid; i < 512; i += 256) sm[EWB + i] = W1[i];
    __syncthreads();

    // ---- layer 1: K=8 -> B ----
    gemm_tile2<8>(sm + EA + nb, sm + EWB + db, Y2);
    store_actT(sm + EB, Y2, nb, db, rsqrtf(8.0f));
    __syncthreads();
    // ---- layer 2: B -> A ----
    for (int i = tid; i < 4096; i += 256) sm[EWB + i] = W2[i];
    __syncthreads();
    gemm_tile2<64>(sm + EB + nb, sm + EWB + db, Y2);
    store_actT(sm + EA, Y2, nb, db, 0.125f);
    __syncthreads();
    // ---- layer 3: A -> B ----
    for (int i = tid; i < 4096; i += 256) sm[EWB + i] = W3[i];
    __syncthreads();
    gemm_tile2<64>(sm + EA + nb, sm + EWB + db, Y2);
    store_actT(sm + EB, Y2, nb, db, 0.125f);
    // (sync happens at first path's weight-stage barrier)

    // ---- per-edge scatter setup ----
    const int e_loc = tid >> 2;
    const int cg = tid & 3;
    const int ch = cg * 16;
    const float i3 = rsqrtf(3.0f), i2 = rsqrtf(2.0f);

    // ---- 5 path GEMMs + scatter ----
#pragma unroll 1
    for (int p = 0; p < 5; p++) {
        __syncthreads();  // prev scatter done reading WSM; prev gemm done reading WB
        for (int i = tid; i < 4096; i += 256)
            sm[EWB + i] = W4[(i >> 6) * 320 + p * 64 + (i & 63)];
        __syncthreads();
        gemm_tile2<64>(sm + EB + nb, sm + EWB + db, Y2);
        // store path weights edge-major, scaled by 1/sqrt(64)
#pragma unroll
        for (int ip = 0; ip < 2; ip++) {
            float y[2][4];
#pragma unroll
            for (int j = 0; j < 4; j++) unpack2(Y2[ip][j], y[0][j], y[1][j]);
#pragma unroll
            for (int h = 0; h < 2; h++)
                *(float4*)(sm + EWSM + (nb + 2*ip + h) * 68 + db) =
                    make_float4(y[h][0]*0.125f, y[h][1]*0.125f, y[h][2]*0.125f, y[h][3]*0.125f);
        }
        __syncthreads();

        // ---- scatter path p: thread = (edge, 16-channel group) ----
        const int s = ((const int*)(sm + EMETA))[e_loc];
        const int r = ((const int*)(sm + EMETA + 64))[e_loc];
        const float sh0v = sm[EMETA + 128 + e_loc];
        const float qx = sm[EMETA + 192 + e_loc];
        const float qy = sm[EMETA + 256 + e_loc];
        const float qz = sm[EMETA + 320 + e_loc];
        const float* wrow = sm + EWSM + e_loc * 68 + ch;
        const float* sep = g_s_scr + s * 64 + ch;
        const float* vp  = g_v_scr + s * 192 + ch;

        if (p == 0) {
            float* dst = g_ms + r * 128 + ch;
#pragma unroll
            for (int g = 0; g < 4; g++) {
                float4 wv = *(const float4*)(wrow + g*4);
                float4 se = *(const float4*)(sep + g*4);
                red4v(dst + g*4, f4muls(f4mul(wv, se), sh0v));
            }
        } else if (p == 1) {
            float* dst = g_ms + r * 128 + 64 + ch;
#pragma unroll
            for (int g = 0; g < 4; g++) {
                float4 wv = *(const float4*)(wrow + g*4);
                float4 vx = *(const float4*)(vp + g*4);
                float4 vy = *(const float4*)(vp + 64 + g*4);
                float4 vz = *(const float4*)(vp + 128 + g*4);
                float4 dt = f4add(f4add(f4muls(vx, qx), f4muls(vy, qy)), f4muls(vz, qz));
                red4v(dst + g*4, f4muls(f4mul(wv, dt), i3));
            }
        } else if (p == 2) {
            float* dst = g_mv + r * 576 + ch * 3;
            float4 aqx = make_float4(qx,qx,qx,qx);
            float4 aqy = make_float4(qy,qy,qy,qy);
            float4 aqz = make_float4(qz,qz,qz,qz);
#pragma unroll
            for (int g = 0; g < 4; g++) {
                float4 wv = *(const float4*)(wrow + g*4);
                float4 se = *(const float4*)(sep + g*4);
                scatter_vec_group(dst + g*12, f4mul(wv, se), aqx, aqy, aqz);
            }
        } else if (p == 3) {
            float* dst = g_mv + r * 576 + 192 + ch * 3;
#pragma unroll
            for (int g = 0; g < 4; g++) {
                float4 wv = *(const float4*)(wrow + g*4);
                float4 vx = *(const float4*)(vp + g*4);
                float4 vy = *(const float4*)(vp + 64 + g*4);
                float4 vz = *(const float4*)(vp + 128 + g*4);
                scatter_vec_group(dst + g*12, f4muls(wv, sh0v), vx, vy, vz);
            }
        } else {
            float* dst = g_mv + r * 576 + 384 + ch * 3;
#pragma unroll
            for (int g = 0; g < 4; g++) {
                float4 wv = *(const float4*)(wrow + g*4);
                float4 vx = *(const float4*)(vp + g*4);
                float4 vy = *(const float4*)(vp + 64 + g*4);
                float4 vz = *(const float4*)(vp + 128 + g*4);
                float4 crx = f4sub(f4muls(vy, qz), f4muls(vz, qy));
                float4 cry = f4sub(f4muls(vz, qx), f4muls(vx, qz));
                float4 crz = f4sub(f4muls(vx, qy), f4muls(vy, qx));
                scatter_vec_group(dst + g*12, f4muls(wv, i2), crx, cry, crz);
            }
        }
    }
}

// ===================== K3: output linear (unchanged) =====================
#define K3_SMEM_BYTES (25344 * 4)
__global__ void __launch_bounds__(256) out_kernel(
    const float* __restrict__ Wouts, const float* __restrict__ Woutv,
    float* __restrict__ out) {
    extern __shared__ float sm[];
    float* msm = sm;
    float* wbuf = sm + 13056;
    const int tid = threadIdx.x;
    const int n0 = blockIdx.x * 64;
    const int tx = tid & 15, ty = tid >> 4;
    const int nb = ty * 4, db = tx * 4;
    u64 Y2[2][4];

    for (int idx = tid; idx < 8192; idx += 256) {
        int n = idx >> 7, k = idx & 127, gn = n0 + n;
        msm[k * 68 + n] = (gn < NNODES) ? g_ms[gn * 128 + k] : 0.0f;
    }
    for (int idx = tid; idx < 8192; idx += 256) wbuf[idx] = Wouts[idx];
    __syncthreads();
    gemm_tile2<128>(msm + nb, wbuf + db, Y2);
    const float ss = rsqrtf(128.0f) / 16.0f;
#pragma unroll
    for (int ip = 0; ip < 2; ip++) {
        float y[2][4];
#pragma unroll
        for (int j = 0; j < 4; j++) unpack2(Y2[ip][j], y[0][j], y[1][j]);
#pragma unroll
        for (int h = 0; h < 2; h++) {
            int gn = n0 + nb + 2*ip + h;
            if (gn < NNODES)
                *(float4*)(out + gn * 64 + db) =
                    make_float4(y[h][0]*ss, y[h][1]*ss, y[h][2]*ss, y[h][3]*ss);
        }
    }
    __syncthreads();
    for (int idx = tid; idx < 12288; idx += 256) wbuf[idx] = Woutv[idx];
    const float sv = rsqrtf(192.0f) / 16.0f;
#pragma unroll 1
    for (int x = 0; x < 3; x++) {
        __syncthreads();
        for (int idx = tid; idx < 12288; idx += 256) {
            int n = idx / 192, k = idx - n * 192, gn = n0 + n;
            msm[k * 68 + n] = (gn < NNODES) ? g_mv[gn * 576 + k * 3 + x] : 0.0f;
        }
        __syncthreads();
        gemm_tile2<192>(msm + nb, wbuf + db, Y2);
#pragma unroll
        for (int ip = 0; ip < 2; ip++) {
            float y[2][4];
#pragma unroll
            for (int j = 0; j < 4; j++) unpack2(Y2[ip][j], y[0][j], y[1][j]);
#pragma unroll
            for (int h = 0; h < 2; h++) {
                int gn = n0 + nb + 2*ip + h;
                if (gn < NNODES)
#pragma unroll
                    for (int j = 0; j < 4; j++)
                        out[OUT_V_OFF + gn * 192 + (db + j) * 3 + x] = y[h][j] * sv;
            }
        }
    }
}

// ===================== launch =====================
extern "C" void kernel_launch(void* const* d_in, const int* in_sizes, int n_in,
                              void* d_out, int out_size) {
    const float* attrs = (const float*)d_in[0];
    const float* fs    = (const float*)d_in[1];
    const float* fv    = (const float*)d_in[2];
    const float* sh0   = (const float*)d_in[3];
    const float* sh1   = (const float*)d_in[4];
    const float* ef    = (const float*)d_in[5];
    const int*   snd   = (const int*)d_in[6];
    const int*   rcv   = (const int*)d_in[7];
    const float* Wscs  = (const float*)d_in[8];
    const float* Wscv  = (const float*)d_in[9];
    const float* Wses  = (const float*)d_in[10];
    const float* Wsev  = (const float*)d_in[11];
    const float* W1    = (const float*)d_in[12];
    const float* W2    = (const float*)d_in[13];
    const float* W3    = (const float*)d_in[14];
    const float* W4    = (const float*)d_in[15];
    const float* Wouts = (const float*)d_in[16];
    const float* Woutv = (const float*)d_in[17];
    float* out = (float*)d_out;

    cudaFuncSetAttribute(node_kernel, cudaFuncAttributeMaxDynamicSharedMemorySize, K1_SMEM_BYTES);
    cudaFuncSetAttribute(edge_kernel, cudaFuncAttributeMaxDynamicSharedMemorySize, K2_SMEM_BYTES);
    cudaFuncSetAttribute(out_kernel,  cudaFuncAttributeMaxDynamicSharedMemorySize, K3_SMEM_BYTES);

    zero_kernel<<<1024, 256>>>();
    node_kernel<<<(NNODES + 63) / 64, 256, K1_SMEM_BYTES>>>(
        attrs, fs, fv, Wscs, Wscv, Wses, Wsev, out);
    edge_kernel<<<NEDGES / 64, 256, K2_SMEM_BYTES>>>(
        ef, sh0, sh1, snd, rcv, W1, W2, W3, W4);
    out_kernel<<<(NNODES + 63) / 64, 256, K3_SMEM_BYTES>>>(Wouts, Woutv, out);
}

// round 10
// speedup vs baseline: 1.5489x; 1.0152x over previous
#include <cuda_runtime.h>

#define NNODES 50000
#define NEDGES 320000
#define NTILES 2500
#define OUT_V_OFF 3200000
#define SC_S_OFF  12800000
#define SC_V_OFF  16000000

typedef unsigned long long u64;

// ---- scratch (__device__ globals: allocation-free) ----
__device__ float g_s_scr[NNODES * 64];
__device__ float g_v_scr[NNODES * 192];   // [n][x][c]
__device__ float g_ms[NNODES * 128];      // [n][2C]
__device__ float g_mv[NNODES * 576];      // [n][3C][3]  (x innermost)

__device__ __forceinline__ float silu_f(float x) { return x / (1.0f + __expf(-x)); }

// ---- packed fp32x2 primitives ----
__device__ __forceinline__ u64 pack2(float lo, float hi) {
    u64 r; asm("mov.b64 %0, {%1, %2};" : "=l"(r) : "f"(lo), "f"(hi)); return r;
}
__device__ __forceinline__ u64 fma2(u64 a, u64 b, u64 c) {
    u64 d; asm("fma.rn.f32x2 %0, %1, %2, %3;" : "=l"(d) : "l"(a), "l"(b), "l"(c)); return d;
}
__device__ __forceinline__ void unpack2(u64 v, float& lo, float& hi) {
    asm("mov.b64 {%0, %1}, %2;" : "=f"(lo), "=f"(hi) : "l"(v));
}

// vectorized f32 reduction (sm_90+): one 16B L2 atomic op
__device__ __forceinline__ void red4v(float* p, float4 v) {
    asm volatile("red.global.add.v4.f32 [%0], {%1, %2, %3, %4};"
                 :: "l"(p), "f"(v.x), "f"(v.y), "f"(v.z), "f"(v.w) : "memory");
}

__device__ __forceinline__ float4 f4mul(float4 a, float4 b) {
    return make_float4(a.x*b.x, a.y*b.y, a.z*b.z, a.w*b.w);
}
__device__ __forceinline__ float4 f4muls(float4 a, float s) {
    return make_float4(a.x*s, a.y*s, a.z*s, a.w*s);
}
__device__ __forceinline__ float4 f4sub(float4 a, float4 b) {
    return make_float4(a.x-b.x, a.y-b.y, a.z-b.z, a.w-b.w);
}
__device__ __forceinline__ float4 f4add(float4 a, float4 b) {
    return make_float4(a.x+b.x, a.y+b.y, a.z+b.z, a.w+b.w);
}

// interleaved vector-path scatter: 12 contiguous floats [4ch x 3xyz] = 3 v4 reds.
__device__ __forceinline__ void scatter_vec_group(float* dst, float4 val,
                                                  float4 ax, float4 ay, float4 az) {
    red4v(dst + 0, make_float4(val.x*ax.x, val.x*ay.x, val.x*az.x, val.y*ax.y));
    red4v(dst + 4, make_float4(val.y*ay.y, val.y*az.y, val.z*ax.z, val.z*ay.z));
    red4v(dst + 8, make_float4(val.z*az.z, val.w*ax.w, val.w*ay.w, val.w*az.w));
}

// 4-row x 4-col register-tile GEMM using packed fp32x2.
// A: [K][LDA] row(edge/node)-contig padded, W: [K][64].
template <int K, int LDA>
__device__ __forceinline__ void gemm_tile2(const float* __restrict__ A,
                                           const float* __restrict__ W,
                                           u64 Y2[2][4]) {
#pragma unroll
    for (int ip = 0; ip < 2; ip++)
#pragma unroll
        for (int j = 0; j < 4; j++) Y2[ip][j] = 0ull;
#pragma unroll 8
    for (int c = 0; c < K; c++) {
        ulonglong2 a2 = *(const ulonglong2*)(A + c * LDA);
        float4 w = *(const float4*)(W + c * 64);
        u64 w0 = pack2(w.x, w.x), w1 = pack2(w.y, w.y);
        u64 w2 = pack2(w.z, w.z), w3 = pack2(w.w, w.w);
        Y2[0][0] = fma2(a2.x, w0, Y2[0][0]);
        Y2[0][1] = fma2(a2.x, w1, Y2[0][1]);
        Y2[0][2] = fma2(a2.x, w2, Y2[0][2]);
        Y2[0][3] = fma2(a2.x, w3, Y2[0][3]);
        Y2[1][0] = fma2(a2.y, w0, Y2[1][0]);
        Y2[1][1] = fma2(a2.y, w1, Y2[1][1]);
        Y2[1][2] = fma2(a2.y, w2, Y2[1][2]);
        Y2[1][3] = fma2(a2.y, w3, Y2[1][3]);
    }
}

// ===================== K0: zero scratch =====================
__global__ void zero_kernel() {
    long i = (long)blockIdx.x * blockDim.x + threadIdx.x;
    long t = (long)gridDim.x * blockDim.x;
    float4 z = make_float4(0.f, 0.f, 0.f, 0.f);
    for (long j = i; j < (long)NNODES * 128 / 4; j += t) ((float4*)g_ms)[j] = z;
    for (long j = i; j < (long)NNODES * 576 / 4; j += t) ((float4*)g_mv)[j] = z;
}

// ===================== K1: node side (unchanged, passing since R5) ==========
#define K1_SMEM_BYTES (22144 * 4)
__global__ void __launch_bounds__(256) node_kernel(
    const float* __restrict__ attrs_g, const float* __restrict__ fs_g,
    const float* __restrict__ fv_g,
    const float* __restrict__ Wscs, const float* __restrict__ Wscv,
    const float* __restrict__ Wses, const float* __restrict__ Wsev,
    float* __restrict__ out) {
    extern __shared__ float sm[];
    float* fsm = sm;
    float* fvm = sm + 4352;
    float* wbuf = sm + 17408;
    float* atm = sm + 21504;
    const int tid = threadIdx.x;
    const int n0 = blockIdx.x * 64;

    for (int idx = tid; idx < 4096; idx += 256) {
        int n = idx >> 6, c = idx & 63, gn = n0 + n;
        fsm[c * 68 + n] = (gn < NNODES) ? fs_g[gn * 64 + c] : 0.0f;
    }
    for (int idx = tid; idx < 12288; idx += 256) {
        int n = idx / 192, r = idx - n * 192, c = r / 3, x = r - c * 3, gn = n0 + n;
        fvm[x * 4352 + c * 68 + n] = (gn < NNODES) ? fv_g[gn * 192 + c * 3 + x] : 0.0f;
    }
    for (int idx = tid; idx < 640; idx += 256) {
        int n = idx / 10, gn = n0 + n;
        atm[idx] = (gn < NNODES) ? attrs_g[gn * 10 + (idx - n * 10)] : 0.0f;
    }

    const int tx = tid & 15, ty = tid >> 4;
    const int nb = ty * 4, db = tx * 4;
    u64 acc_s[2][4], acc_v[3][2][4], Y2[2][4];
#pragma unroll
    for (int ip = 0; ip < 2; ip++)
#pragma unroll
        for (int j = 0; j < 4; j++) acc_s[ip][j] = 0ull;
#pragma unroll
    for (int x = 0; x < 3; x++)
#pragma unroll
        for (int ip = 0; ip < 2; ip++)
#pragma unroll
            for (int j = 0; j < 4; j++) acc_v[x][ip][j] = 0ull;

    for (int a = 0; a < 10; a++) {
        __syncthreads();
        for (int idx = tid; idx < 4096; idx += 256)
            wbuf[idx] = Wscs[((idx >> 6) * 10 + a) * 64 + (idx & 63)];
        __syncthreads();
        gemm_tile2<64, 68>(fsm + nb, wbuf + db, Y2);
#pragma unroll
        for (int ip = 0; ip < 2; ip++) {
            u64 av2 = pack2(atm[(nb + 2*ip) * 10 + a], atm[(nb + 2*ip + 1) * 10 + a]);
#pragma unroll
            for (int j = 0; j < 4; j++) acc_s[ip][j] = fma2(av2, Y2[ip][j], acc_s[ip][j]);
        }
    }
    for (int a = 0; a < 10; a++) {
        __syncthreads();
        for (int idx = tid; idx < 4096; idx += 256)
            wbuf[idx] = Wscv[((idx >> 6) * 10 + a) * 64 + (idx & 63)];
        __syncthreads();
#pragma unroll 1
        for (int x = 0; x < 3; x++) {
            gemm_tile2<64, 68>(fvm + x * 4352 + nb, wbuf + db, Y2);
#pragma unroll
            for (int ip = 0; ip < 2; ip++) {
                u64 av2 = pack2(atm[(nb + 2*ip) * 10 + a], atm[(nb + 2*ip + 1) * 10 + a]);
#pragma unroll
                for (int j = 0; j < 4; j++) acc_v[x][ip][j] = fma2(av2, Y2[ip][j], acc_v[x][ip][j]);
            }
        }
    }
    __syncthreads();
    for (int idx = tid; idx < 4096; idx += 256) wbuf[idx] = Wses[idx];
    __syncthreads();
    gemm_tile2<64, 68>(fsm + nb, wbuf + db, Y2);
#pragma unroll
    for (int ip = 0; ip < 2; ip++) {
        float y[2][4];
#pragma unroll
        for (int j = 0; j < 4; j++) unpack2(Y2[ip][j], y[0][j], y[1][j]);
#pragma unroll
        for (int h = 0; h < 2; h++) {
            int gn = n0 + nb + 2*ip + h;
            if (gn < NNODES)
                *(float4*)(g_s_scr + gn * 64 + db) =
                    make_float4(y[h][0]*0.125f, y[h][1]*0.125f, y[h][2]*0.125f, y[h][3]*0.125f);
        }
    }
    __syncthreads();
    for (int idx = tid; idx < 4096; idx += 256) wbuf[idx] = Wsev[idx];
    __syncthreads();
#pragma unroll 1
    for (int x = 0; x < 3; x++) {
        gemm_tile2<64, 68>(fvm + x * 4352 + nb, wbuf + db, Y2);
#pragma unroll
        for (int ip = 0; ip < 2; ip++) {
            float y[2][4];
#pragma unroll
            for (int j = 0; j < 4; j++) unpack2(Y2[ip][j], y[0][j], y[1][j]);
#pragma unroll
            for (int h = 0; h < 2; h++) {
                int gn = n0 + nb + 2*ip + h;
                if (gn < NNODES)
                    *(float4*)(g_v_scr + gn * 192 + x * 64 + db) =
                        make_float4(y[h][0]*0.125f, y[h][1]*0.125f, y[h][2]*0.125f, y[h][3]*0.125f);
            }
        }
    }
    const float isc = rsqrtf(640.0f);
#pragma unroll
    for (int ip = 0; ip < 2; ip++) {
        float ys[2][4], yv[3][2][4];
#pragma unroll
        for (int j = 0; j < 4; j++) {
            unpack2(acc_s[ip][j], ys[0][j], ys[1][j]);
#pragma unroll
            for (int x = 0; x < 3; x++) unpack2(acc_v[x][ip][j], yv[x][0][j], yv[x][1][j]);
        }
#pragma unroll
        for (int h = 0; h < 2; h++) {
            int gn = n0 + nb + 2*ip + h;
            if (gn < NNODES) {
                *(float4*)(out + SC_S_OFF + gn * 64 + db) =
                    make_float4(ys[h][0]*isc, ys[h][1]*isc, ys[h][2]*isc, ys[h][3]*isc);
#pragma unroll
                for (int j = 0; j < 4; j++)
#pragma unroll
                    for (int x = 0; x < 3; x++)
                        out[SC_V_OFF + (gn * 64 + db + j) * 3 + x] = yv[x][h][j] * isc;
            }
        }
    }
}

// ===================== K2: edge side, persistent CTAs + resident weights ====
// 512 threads, 128-edge tiles, ~16 tiles per CTA. smem (floats):
//   SA @0      (8960)  acts A, k-major [64][140]; reused as WSM [128][68]
//   SB @8960   (8960)  acts B, k-major [64][140]
//   SW1 @17920 (512)   W1 [8][64]
//   SW2 @18432 (4096)  W2 [64][64]
//   SW3 @22528 (4096)  W3 [64][64]
//   SW4 @26624 (20480) W4 re-laid [5][64][64]
//   SMETA @47104 (768) s[128] r[128] sh0[128] qx qy qz
#define SA 0
#define SB 8960
#define SW1 17920
#define SW2 18432
#define SW3 22528
#define SW4 26624
#define SMETA 47104
#define K2_SMEM_BYTES (47872 * 4)

// transposed (k-major) activation store with silu; edge-pair as one float2.
__device__ __forceinline__ void store_actT(float* dst, const u64 Y2[2][4],
                                           int nb, int db, float scale) {
#pragma unroll
    for (int ip = 0; ip < 2; ip++)
#pragma unroll
        for (int j = 0; j < 4; j++) {
            float lo, hi; unpack2(Y2[ip][j], lo, hi);
            *(float2*)(dst + (db + j) * 140 + nb + 2*ip) =
                make_float2(silu_f(lo * scale), silu_f(hi * scale));
        }
}

__global__ void __launch_bounds__(512, 1) edge_kernel(
    const float* __restrict__ ef_g, const float* __restrict__ sh0_g,
    const float* __restrict__ sh1_g, const int* __restrict__ snd_g,
    const int* __restrict__ rcv_g,
    const float* __restrict__ W1, const float* __restrict__ W2,
    const float* __restrict__ W3, const float* __restrict__ W4) {
    extern __shared__ float sm[];
    const int tid = threadIdx.x;
    const int tx = tid & 15, ty = tid >> 4;       // ty 0..31 (edge grps), tx (d grps)
    const int nb = ty * 4, db = tx * 4;
    const int e_loc = tid >> 2, cg = tid & 3, ch = cg * 16;
    const float i3 = rsqrtf(3.0f), i2 = rsqrtf(2.0f), is8 = rsqrtf(8.0f);
    u64 Y2[2][4];

    // ---- stage ALL weights once per CTA ----
    if (tid < 512) sm[SW1 + tid] = W1[tid];
    for (int i = tid; i < 4096; i += 512) sm[SW2 + i] = W2[i];
    for (int i = tid; i < 4096; i += 512) sm[SW3 + i] = W3[i];
    for (int i = tid; i < 20480; i += 512) {
        int p = i >> 12, rem = i & 4095, k = rem >> 6, d = rem & 63;
        sm[SW4 + i] = W4[k * 320 + p * 64 + d];
    }

    for (int t = blockIdx.x; t < NTILES; t += gridDim.x) {
        const int e0 = t * 128;
        __syncthreads();   // covers weight staging (1st iter) + prev tile's SA/SB readers

        // ---- stage tile: meta + ef (k-major into SA) ----
        if (tid < 128) {
            int ge = e0 + tid;
            ((int*)(sm + SMETA))[tid]       = snd_g[ge];
            ((int*)(sm + SMETA + 128))[tid] = rcv_g[ge];
            sm[SMETA + 256 + tid] = sh0_g[ge];
            sm[SMETA + 384 + tid] = sh1_g[ge * 3 + 0];
            sm[SMETA + 512 + tid] = sh1_g[ge * 3 + 1];
            sm[SMETA + 640 + tid] = sh1_g[ge * 3 + 2];
        }
        for (int i = tid; i < 1024; i += 512) {
            int e = i >> 3, k = i & 7;
            sm[SA + k * 140 + e] = ef_g[e0 * 8 + i];
        }
        __syncthreads();

        // ---- MLP: L1 (SA->SB), L2 (SB->SA), L3 (SA->SB) ----
        gemm_tile2<8, 140>(sm + SA + nb, sm + SW1 + db, Y2);
        store_actT(sm + SB, Y2, nb, db, is8);
        __syncthreads();
        gemm_tile2<64, 140>(sm + SB + nb, sm + SW2 + db, Y2);
        store_actT(sm + SA, Y2, nb, db, 0.125f);
        __syncthreads();
        gemm_tile2<64, 140>(sm + SA + nb, sm + SW3 + db, Y2);
        store_actT(sm + SB, Y2, nb, db, 0.125f);
        __syncthreads();   // SB = h3 ready; SA free for WSM

        // per-tile scatter constants
        const int s = ((const int*)(sm + SMETA))[e_loc];
        const int r = ((const int*)(sm + SMETA + 128))[e_loc];
        const float sh0v = sm[SMETA + 256 + e_loc];
        const float qx = sm[SMETA + 384 + e_loc];
        const float qy = sm[SMETA + 512 + e_loc];
        const float qz = sm[SMETA + 640 + e_loc];
        const float* sep = g_s_scr + s * 64 + ch;
        const float* vp  = g_v_scr + s * 192 + ch;

        // ---- 5 path GEMMs + scatters ----
#pragma unroll 1
        for (int p = 0; p < 5; p++) {
            gemm_tile2<64, 140>(sm + SB + nb, sm + SW4 + p * 4096 + db, Y2);
            // path weights -> WSM (=SA), edge-major [128][68], scaled 1/8
#pragma unroll
            for (int ip = 0; ip < 2; ip++) {
                float y[2][4];
#pragma unroll
                for (int j = 0; j < 4; j++) unpack2(Y2[ip][j], y[0][j], y[1][j]);
#pragma unroll
                for (int h = 0; h < 2; h++)
                    *(float4*)(sm + SA + (nb + 2*ip + h) * 68 + db) =
                        make_float4(y[h][0]*0.125f, y[h][1]*0.125f,
                                    y[h][2]*0.125f, y[h][3]*0.125f);
            }
            __syncthreads();

            const float* wrow = sm + SA + e_loc * 68 + ch;
            if (p == 0) {
                float* dst = g_ms + r * 128 + ch;
#pragma unroll
                for (int g = 0; g < 4; g++) {
                    float4 wv = *(const float4*)(wrow + g*4);
                    float4 se = *(const float4*)(sep + g*4);
                    red4v(dst + g*4, f4muls(f4mul(wv, se), sh0v));
                }
            } else if (p == 1) {
                float* dst = g_ms + r * 128 + 64 + ch;
#pragma unroll
                for (int g = 0; g < 4; g++) {
                    float4 wv = *(const float4*)(wrow + g*4);
                    float4 vx = *(const float4*)(vp + g*4);
                    float4 vy = *(const float4*)(vp + 64 + g*4);
                    float4 vz = *(const float4*)(vp + 128 + g*4);
                    float4 dt = f4add(f4add(f4muls(vx, qx), f4muls(vy, qy)), f4muls(vz, qz));
                    red4v(dst + g*4, f4muls(f4mul(wv, dt), i3));
                }
            } else if (p == 2) {
                float* dst = g_mv + r * 576 + ch * 3;
                float4 aqx = make_float4(qx,qx,qx,qx);
                float4 aqy = make_float4(qy,qy,qy,qy);
                float4 aqz = make_float4(qz,qz,qz,qz);
#pragma unroll
                for (int g = 0; g < 4; g++) {
                    float4 wv = *(const float4*)(wrow + g*4);
                    float4 se = *(const float4*)(sep + g*4);
                    scatter_vec_group(dst + g*12, f4mul(wv, se), aqx, aqy, aqz);
                }
            } else if (p == 3) {
                float* dst = g_mv + r * 576 + 192 + ch * 3;
#pragma unroll
                for (int g = 0; g < 4; g++) {
                    float4 wv = *(const float4*)(wrow + g*4);
                    float4 vx = *(const float4*)(vp + g*4);
                    float4 vy = *(const float4*)(vp + 64 + g*4);
                    float4 vz = *(const float4*)(vp + 128 + g*4);
                    scatter_vec_group(dst + g*12, f4muls(wv, sh0v), vx, vy, vz);
                }
            } else {
                float* dst = g_mv + r * 576 + 384 + ch * 3;
#pragma unroll
                for (int g = 0; g < 4; g++) {
                    float4 wv = *(const float4*)(wrow + g*4);
                    float4 vx = *(const float4*)(vp + g*4);
                    float4 vy = *(const float4*)(vp + 64 + g*4);
                    float4 vz = *(const float4*)(vp + 128 + g*4);
                    float4 crx = f4sub(f4muls(vy, qz), f4muls(vz, qy));
                    float4 cry = f4sub(f4muls(vz, qx), f4muls(vx, qz));
                    float4 crz = f4sub(f4muls(vx, qy), f4muls(vy, qx));
                    scatter_vec_group(dst + g*12, f4muls(wv, i2), crx, cry, crz);
                }
            }
            if (p < 4) __syncthreads();  // scatter done reading WSM before next store
        }
    }
}

// ===================== K3: output linear (unchanged) =====================
#define K3_SMEM_BYTES (25344 * 4)
__global__ void __launch_bounds__(256) out_kernel(
    const float* __restrict__ Wouts, const float* __restrict__ Woutv,
    float* __restrict__ out) {
    extern __shared__ float sm[];
    float* msm = sm;
    float* wbuf = sm + 13056;
    const int tid = threadIdx.x;
    const int n0 = blockIdx.x * 64;
    const int tx = tid & 15, ty = tid >> 4;
    const int nb = ty * 4, db = tx * 4;
    u64 Y2[2][4];

    for (int idx = tid; idx < 8192; idx += 256) {
        int n = idx >> 7, k = idx & 127, gn = n0 + n;
        msm[k * 68 + n] = (gn < NNODES) ? g_ms[gn * 128 + k] : 0.0f;
    }
    for (int idx = tid; idx < 8192; idx += 256) wbuf[idx] = Wouts[idx];
    __syncthreads();
    gemm_tile2<128, 68>(msm + nb, wbuf + db, Y2);
    const float ss = rsqrtf(128.0f) / 16.0f;
#pragma unroll
    for (int ip = 0; ip < 2; ip++) {
        float y[2][4];
#pragma unroll
        for (int j = 0; j < 4; j++) unpack2(Y2[ip][j], y[0][j], y[1][j]);
#pragma unroll
        for (int h = 0; h < 2; h++) {
            int gn = n0 + nb + 2*ip + h;
            if (gn < NNODES)
                *(float4*)(out + gn * 64 + db) =
                    make_float4(y[h][0]*ss, y[h][1]*ss, y[h][2]*ss, y[h][3]*ss);
        }
    }
    __syncthreads();
    for (int idx = tid; idx < 12288; idx += 256) wbuf[idx] = Woutv[idx];
    const float sv = rsqrtf(192.0f) / 16.0f;
#pragma unroll 1
    for (int x = 0; x < 3; x++) {
        __syncthreads();
        for (int idx = tid; idx < 12288; idx += 256) {
            int n = idx / 192, k = idx - n * 192, gn = n0 + n;
            msm[k * 68 + n] = (gn < NNODES) ? g_mv[gn * 576 + k * 3 + x] : 0.0f;
        }
        __syncthreads();
        gemm_tile2<192, 68>(msm + nb, wbuf + db, Y2);
#pragma unroll
        for (int ip = 0; ip < 2; ip++) {
            float y[2][4];
#pragma unroll
            for (int j = 0; j < 4; j++) unpack2(Y2[ip][j], y[0][j], y[1][j]);
#pragma unroll
            for (int h = 0; h < 2; h++) {
                int gn = n0 + nb + 2*ip + h;
                if (gn < NNODES)
#pragma unroll
                    for (int j = 0; j < 4; j++)
                        out[OUT_V_OFF + gn * 192 + (db + j) * 3 + x] = y[h][j] * sv;
            }
        }
    }
}

// ===================== launch =====================
extern "C" void kernel_launch(void* const* d_in, const int* in_sizes, int n_in,
                              void* d_out, int out_size) {
    const float* attrs = (const float*)d_in[0];
    const float* fs    = (const float*)d_in[1];
    const float* fv    = (const float*)d_in[2];
    const float* sh0   = (const float*)d_in[3];
    const float* sh1   = (const float*)d_in[4];
    const float* ef    = (const float*)d_in[5];
    const int*   snd   = (const int*)d_in[6];
    const int*   rcv   = (const int*)d_in[7];
    const float* Wscs  = (const float*)d_in[8];
    const float* Wscv  = (const float*)d_in[9];
    const float* Wses  = (const float*)d_in[10];
    const float* Wsev  = (const float*)d_in[11];
    const float* W1    = (const float*)d_in[12];
    const float* W2    = (const float*)d_in[13];
    const float* W3    = (const float*)d_in[14];
    const float* W4    = (const float*)d_in[15];
    const float* Wouts = (const float*)d_in[16];
    const float* Woutv = (const float*)d_in[17];
    float* out = (float*)d_out;

    cudaFuncSetAttribute(node_kernel, cudaFuncAttributeMaxDynamicSharedMemorySize, K1_SMEM_BYTES);
    cudaFuncSetAttribute(edge_kernel, cudaFuncAttributeMaxDynamicSharedMemorySize, K2_SMEM_BYTES);
    cudaFuncSetAttribute(out_kernel,  cudaFuncAttributeMaxDynamicSharedMemorySize, K3_SMEM_BYTES);

    zero_kernel<<<1024, 256>>>();
    node_kernel<<<(NNODES + 63) / 64, 256, K1_SMEM_BYTES>>>(
        attrs, fs, fv, Wscs, Wscv, Wses, Wsev, out);
    edge_kernel<<<152, 512, K2_SMEM_BYTES>>>(
        ef, sh0, sh1, snd, rcv, W1, W2, W3, W4);
    out_kernel<<<(NNODES + 63) / 64, 256, K3_SMEM_BYTES>>>(Wouts, Woutv, out);
}

// round 11
// speedup vs baseline: 1.6899x; 1.0910x over previous
#include <cuda_runtime.h>

#define NNODES 50000
#define NEDGES 320000
#define OUT_V_OFF 3200000
#define SC_S_OFF  12800000
#define SC_V_OFF  16000000

typedef unsigned long long u64;

// ---- scratch (__device__ globals: allocation-free) ----
__device__ float g_s_scr[NNODES * 64];
__device__ float g_v_scr[NNODES * 192];   // [n][x][c]
__device__ float g_ms[NNODES * 128];      // [n][2C]
__device__ float g_mv[NNODES * 576];      // [n][3C][3]  (x innermost)

__device__ __forceinline__ float silu_f(float x) { return x / (1.0f + __expf(-x)); }

// ---- packed fp32x2 primitives ----
__device__ __forceinline__ u64 pack2(float lo, float hi) {
    u64 r; asm("mov.b64 %0, {%1, %2};" : "=l"(r) : "f"(lo), "f"(hi)); return r;
}
__device__ __forceinline__ u64 fma2(u64 a, u64 b, u64 c) {
    u64 d; asm("fma.rn.f32x2 %0, %1, %2, %3;" : "=l"(d) : "l"(a), "l"(b), "l"(c)); return d;
}
__device__ __forceinline__ void unpack2(u64 v, float& lo, float& hi) {
    asm("mov.b64 {%0, %1}, %2;" : "=f"(lo), "=f"(hi) : "l"(v));
}

// vectorized f32 reduction (sm_90+): one 16B L2 atomic op
__device__ __forceinline__ void red4v(float* p, float4 v) {
    asm volatile("red.global.add.v4.f32 [%0], {%1, %2, %3, %4};"
                 :: "l"(p), "f"(v.x), "f"(v.y), "f"(v.z), "f"(v.w) : "memory");
}

// ---- cp.async helpers ----
__device__ __forceinline__ unsigned smaddr(const void* p) {
    return (unsigned)__cvta_generic_to_shared(p);
}
__device__ __forceinline__ void cp16(unsigned dst, const float* src) {
    asm volatile("cp.async.cg.shared.global [%0], [%1], 16;" :: "r"(dst), "l"(src) : "memory");
}
__device__ __forceinline__ void cp_commit() {
    asm volatile("cp.async.commit_group;" ::: "memory");
}

__device__ __forceinline__ float4 f4mul(float4 a, float4 b) {
    return make_float4(a.x*b.x, a.y*b.y, a.z*b.z, a.w*b.w);
}
__device__ __forceinline__ float4 f4muls(float4 a, float s) {
    return make_float4(a.x*s, a.y*s, a.z*s, a.w*s);
}
__device__ __forceinline__ float4 f4sub(float4 a, float4 b) {
    return make_float4(a.x-b.x, a.y-b.y, a.z-b.z, a.w-b.w);
}
__device__ __forceinline__ float4 f4add(float4 a, float4 b) {
    return make_float4(a.x+b.x, a.y+b.y, a.z+b.z, a.w+b.w);
}

// interleaved vector-path scatter: 12 contiguous floats [4ch x 3xyz] = 3 v4 reds.
__device__ __forceinline__ void scatter_vec_group(float* dst, float4 val,
                                                  float4 ax, float4 ay, float4 az) {
    red4v(dst + 0, make_float4(val.x*ax.x, val.x*ay.x, val.x*az.x, val.y*ax.y));
    red4v(dst + 4, make_float4(val.y*ay.y, val.y*az.y, val.z*ax.z, val.z*ay.z));
    red4v(dst + 8, make_float4(val.z*az.z, val.w*ax.w, val.w*ay.w, val.w*az.w));
}

// 4-row x 4-col register-tile GEMM using packed fp32x2.
// A: [K][LDA] row(edge/node)-contig padded, W: [K][64].
template <int K, int LDA>
__device__ __forceinline__ void gemm_tile2(const float* __restrict__ A,
                                           const float* __restrict__ W,
                                           u64 Y2[2][4]) {
#pragma unroll
    for (int ip = 0; ip < 2; ip++)
#pragma unroll
        for (int j = 0; j < 4; j++) Y2[ip][j] = 0ull;
#pragma unroll 8
    for (int c = 0; c < K; c++) {
        ulonglong2 a2 = *(const ulonglong2*)(A + c * LDA);
        float4 w = *(const float4*)(W + c * 64);
        u64 w0 = pack2(w.x, w.x), w1 = pack2(w.y, w.y);
        u64 w2 = pack2(w.z, w.z), w3 = pack2(w.w, w.w);
        Y2[0][0] = fma2(a2.x, w0, Y2[0][0]);
        Y2[0][1] = fma2(a2.x, w1, Y2[0][1]);
        Y2[0][2] = fma2(a2.x, w2, Y2[0][2]);
        Y2[0][3] = fma2(a2.x, w3, Y2[0][3]);
        Y2[1][0] = fma2(a2.y, w0, Y2[1][0]);
        Y2[1][1] = fma2(a2.y, w1, Y2[1][1]);
        Y2[1][2] = fma2(a2.y, w2, Y2[1][2]);
        Y2[1][3] = fma2(a2.y, w3, Y2[1][3]);
    }
}

// ===================== K0: zero scratch =====================
__global__ void zero_kernel() {
    long i = (long)blockIdx.x * blockDim.x + threadIdx.x;
    long t = (long)gridDim.x * blockDim.x;
    float4 z = make_float4(0.f, 0.f, 0.f, 0.f);
    for (long j = i; j < (long)NNODES * 128 / 4; j += t) ((float4*)g_ms)[j] = z;
    for (long j = i; j < (long)NNODES * 576 / 4; j += t) ((float4*)g_mv)[j] = z;
}

// ===================== K1: node side (logic unchanged, passing) ==========
#define K1_SMEM_BYTES (22144 * 4)
__global__ void __launch_bounds__(256, 2) node_kernel(
    const float* __restrict__ attrs_g, const float* __restrict__ fs_g,
    const float* __restrict__ fv_g,
    const float* __restrict__ Wscs, const float* __restrict__ Wscv,
    const float* __restrict__ Wses, const float* __restrict__ Wsev,
    float* __restrict__ out) {
    extern __shared__ float sm[];
    float* fsm = sm;
    float* fvm = sm + 4352;
    float* wbuf = sm + 17408;
    float* atm = sm + 21504;
    const int tid = threadIdx.x;
    const int n0 = blockIdx.x * 64;

    for (int idx = tid; idx < 4096; idx += 256) {
        int n = idx >> 6, c = idx & 63, gn = n0 + n;
        fsm[c * 68 + n] = (gn < NNODES) ? fs_g[gn * 64 + c] : 0.0f;
    }
    for (int idx = tid; idx < 12288; idx += 256) {
        int n = idx / 192, r = idx - n * 192, c = r / 3, x = r - c * 3, gn = n0 + n;
        fvm[x * 4352 + c * 68 + n] = (gn < NNODES) ? fv_g[gn * 192 + c * 3 + x] : 0.0f;
    }
    for (int idx = tid; idx < 640; idx += 256) {
        int n = idx / 10, gn = n0 + n;
        atm[idx] = (gn < NNODES) ? attrs_g[gn * 10 + (idx - n * 10)] : 0.0f;
    }

    const int tx = tid & 15, ty = tid >> 4;
    const int nb = ty * 4, db = tx * 4;
    u64 acc_s[2][4], acc_v[3][2][4], Y2[2][4];
#pragma unroll
    for (int ip = 0; ip < 2; ip++)
#pragma unroll
        for (int j = 0; j < 4; j++) acc_s[ip][j] = 0ull;
#pragma unroll
    for (int x = 0; x < 3; x++)
#pragma unroll
        for (int ip = 0; ip < 2; ip++)
#pragma unroll
            for (int j = 0; j < 4; j++) acc_v[x][ip][j] = 0ull;

    for (int a = 0; a < 10; a++) {
        __syncthreads();
        for (int idx = tid; idx < 4096; idx += 256)
            wbuf[idx] = Wscs[((idx >> 6) * 10 + a) * 64 + (idx & 63)];
        __syncthreads();
        gemm_tile2<64, 68>(fsm + nb, wbuf + db, Y2);
#pragma unroll
        for (int ip = 0; ip < 2; ip++) {
            u64 av2 = pack2(atm[(nb + 2*ip) * 10 + a], atm[(nb + 2*ip + 1) * 10 + a]);
#pragma unroll
            for (int j = 0; j < 4; j++) acc_s[ip][j] = fma2(av2, Y2[ip][j], acc_s[ip][j]);
        }
    }
    for (int a = 0; a < 10; a++) {
        __syncthreads();
        for (int idx = tid; idx < 4096; idx += 256)
            wbuf[idx] = Wscv[((idx >> 6) * 10 + a) * 64 + (idx & 63)];
        __syncthreads();
#pragma unroll 1
        for (int x = 0; x < 3; x++) {
            gemm_tile2<64, 68>(fvm + x * 4352 + nb, wbuf + db, Y2);
#pragma unroll
            for (int ip = 0; ip < 2; ip++) {
                u64 av2 = pack2(atm[(nb + 2*ip) * 10 + a], atm[(nb + 2*ip + 1) * 10 + a]);
#pragma unroll
                for (int j = 0; j < 4; j++) acc_v[x][ip][j] = fma2(av2, Y2[ip][j], acc_v[x][ip][j]);
            }
        }
    }
    __syncthreads();
    for (int idx = tid; idx < 4096; idx += 256) wbuf[idx] = Wses[idx];
    __syncthreads();
    gemm_tile2<64, 68>(fsm + nb, wbuf + db, Y2);
#pragma unroll
    for (int ip = 0; ip < 2; ip++) {
        float y[2][4];
#pragma unroll
        for (int j = 0; j < 4; j++) unpack2(Y2[ip][j], y[0][j], y[1][j]);
#pragma unroll
        for (int h = 0; h < 2; h++) {
            int gn = n0 + nb + 2*ip + h;
            if (gn < NNODES)
                *(float4*)(g_s_scr + gn * 64 + db) =
                    make_float4(y[h][0]*0.125f, y[h][1]*0.125f, y[h][2]*0.125f, y[h][3]*0.125f);
        }
    }
    __syncthreads();
    for (int idx = tid; idx < 4096; idx += 256) wbuf[idx] = Wsev[idx];
    __syncthreads();
#pragma unroll 1
    for (int x = 0; x < 3; x++) {
        gemm_tile2<64, 68>(fvm + x * 4352 + nb, wbuf + db, Y2);
#pragma unroll
        for (int ip = 0; ip < 2; ip++) {
            float y[2][4];
#pragma unroll
            for (int j = 0; j < 4; j++) unpack2(Y2[ip][j], y[0][j], y[1][j]);
#pragma unroll
            for (int h = 0; h < 2; h++) {
                int gn = n0 + nb + 2*ip + h;
                if (gn < NNODES)
                    *(float4*)(g_v_scr + gn * 192 + x * 64 + db) =
                        make_float4(y[h][0]*0.125f, y[h][1]*0.125f, y[h][2]*0.125f, y[h][3]*0.125f);
            }
        }
    }
    const float isc = rsqrtf(640.0f);
#pragma unroll
    for (int ip = 0; ip < 2; ip++) {
        float ys[2][4], yv[3][2][4];
#pragma unroll
        for (int j = 0; j < 4; j++) {
            unpack2(acc_s[ip][j], ys[0][j], ys[1][j]);
#pragma unroll
            for (int x = 0; x < 3; x++) unpack2(acc_v[x][ip][j], yv[x][0][j], yv[x][1][j]);
        }
#pragma unroll
        for (int h = 0; h < 2; h++) {
            int gn = n0 + nb + 2*ip + h;
            if (gn < NNODES) {
                *(float4*)(out + SC_S_OFF + gn * 64 + db) =
                    make_float4(ys[h][0]*isc, ys[h][1]*isc, ys[h][2]*isc, ys[h][3]*isc);
#pragma unroll
                for (int j = 0; j < 4; j++)
#pragma unroll
                    for (int x = 0; x < 3; x++)
                        out[SC_V_OFF + (gn * 64 + db + j) * 3 + x] = yv[x][h][j] * isc;
            }
        }
    }
}

// ===================== K2: edge side — 2 CTAs/SM + cp.async weight pipeline
// 512 threads, 128-edge tile per CTA (grid 2500). smem (floats):
//   SA  @0      (8960) acts A [64][140]; reused as WSM [128][68]
//   SB  @8960   (8960) acts B [64][140]  (holds h3 during paths)
//   SW1 @17920  (512)  W1 resident
//   WS0 @18432  (4096) weight stage buf 0
//   WS1 @22528  (4096) weight stage buf 1
//   META@26624  (768)
// total 27392 floats = 109.6 KB -> 2 CTAs/SM (8 warps/SMSP)
#define SA 0
#define SB 8960
#define SW1 17920
#define WS0 18432
#define WS1 22528
#define SMETA 26624
#define K2_SMEM_BYTES (27392 * 4)

// transposed (k-major) activation store with silu; edge-pair as one float2.
__device__ __forceinline__ void store_actT(float* dst, const u64 Y2[2][4],
                                           int nb, int db, float scale) {
#pragma unroll
    for (int ip = 0; ip < 2; ip++)
#pragma unroll
        for (int j = 0; j < 4; j++) {
            float lo, hi; unpack2(Y2[ip][j], lo, hi);
            *(float2*)(dst + (db + j) * 140 + nb + 2*ip) =
                make_float2(silu_f(lo * scale), silu_f(hi * scale));
        }
}

// stage one 64x64 weight panel (16KB) via cp.async; commits one group.
__device__ __forceinline__ void stage_w64(float* dst, const float* src,
                                          int ld_src, int col0, int tid) {
#pragma unroll
    for (int i = tid; i < 1024; i += 512) {
        int k = i >> 4, c4 = (i & 15) * 4;
        cp16(smaddr(dst + k * 64 + c4), src + k * ld_src + col0 + c4);
    }
    cp_commit();
}

__global__ void __launch_bounds__(512, 2) edge_kernel(
    const float* __restrict__ ef_g, const float* __restrict__ sh0_g,
    const float* __restrict__ sh1_g, const int* __restrict__ snd_g,
    const int* __restrict__ rcv_g,
    const float* __restrict__ W1, const float* __restrict__ W2,
    const float* __restrict__ W3, const float* __restrict__ W4) {
    extern __shared__ float sm[];
    const int tid = threadIdx.x;
    const int e0 = blockIdx.x * 128;
    const int tx = tid & 15, ty = tid >> 4;
    const int nb = ty * 4, db = tx * 4;
    const int e_loc = tid >> 2, cg = tid & 3, ch = cg * 16;
    const float i3 = rsqrtf(3.0f), i2 = rsqrtf(2.0f), is8 = rsqrtf(8.0f);
    u64 Y2[2][4];

    // ---- stage tile: meta + ef (k-major into SA) + W1; launch W2/W3 async ----
    if (tid < 128) {
        int ge = e0 + tid;
        ((int*)(sm + SMETA))[tid]       = snd_g[ge];
        ((int*)(sm + SMETA + 128))[tid] = rcv_g[ge];
        sm[SMETA + 256 + tid] = sh0_g[ge];
        sm[SMETA + 384 + tid] = sh1_g[ge * 3 + 0];
        sm[SMETA + 512 + tid] = sh1_g[ge * 3 + 1];
        sm[SMETA + 640 + tid] = sh1_g[ge * 3 + 2];
    }
    for (int i = tid; i < 1024; i += 512) {
        int e = i >> 3, k = i & 7;
        sm[SA + k * 140 + e] = ef_g[e0 * 8 + i];
    }
    sm[SW1 + tid] = W1[tid];
    stage_w64(sm + WS0, W2, 64, 0, tid);   // group g1
    stage_w64(sm + WS1, W3, 64, 0, tid);   // group g2
    __syncthreads();                        // ef, meta, W1 visible

    // ---- L1: SA -> SB (resident W1) ----
    gemm_tile2<8, 140>(sm + SA + nb, sm + SW1 + db, Y2);
    store_actT(sm + SB, Y2, nb, db, is8);
    asm volatile("cp.async.wait_group 1;" ::: "memory");   // my W2 chunks done
    __syncthreads();                        // W2 visible to all; SB visible

    // ---- L2: SB -> SA (WS0 = W2) ----
    gemm_tile2<64, 140>(sm + SB + nb, sm + WS0 + db, Y2);
    store_actT(sm + SA, Y2, nb, db, 0.125f);
    asm volatile("cp.async.wait_group 0;" ::: "memory");   // W3 done
    __syncthreads();                        // W3 visible; SA visible; WS0 free
    stage_w64(sm + WS0, W4, 320, 0 * 64, tid);   // g3: W4 path0 -> WS0

    // ---- L3: SA -> SB (WS1 = W3) ----
    gemm_tile2<64, 140>(sm + SA + nb, sm + WS1 + db, Y2);
    store_actT(sm + SB, Y2, nb, db, 0.125f);
    __syncthreads();                        // SB (h3) visible; WS1 free
    stage_w64(sm + WS1, W4, 320, 1 * 64, tid);   // g4: W4 path1 -> WS1

    // ---- per-edge scatter constants ----
    const int s = ((const int*)(sm + SMETA))[e_loc];
    const int r = ((const int*)(sm + SMETA + 128))[e_loc];
    const float sh0v = sm[SMETA + 256 + e_loc];
    const float qx = sm[SMETA + 384 + e_loc];
    const float qy = sm[SMETA + 512 + e_loc];
    const float qz = sm[SMETA + 640 + e_loc];
    const float* sep = g_s_scr + s * 64 + ch;
    const float* vp  = g_v_scr + s * 192 + ch;

    // ---- 5 path GEMMs + scatters, double-buffered panels ----
#pragma unroll 1
    for (int p = 0; p < 5; p++) {
        float* buf = sm + ((p & 1) ? WS1 : WS0);
        if (p < 4) asm volatile("cp.async.wait_group 1;" ::: "memory");
        else       asm volatile("cp.async.wait_group 0;" ::: "memory");
        __syncthreads();   // panel visible to all; prev scatter done reading WSM

        gemm_tile2<64, 140>(sm + SB + nb, buf + db, Y2);
        // path weights -> WSM (=SA), edge-major [128][68], scaled 1/8
#pragma unroll
        for (int ip = 0; ip < 2; ip++) {
            float y[2][4];
#pragma unroll
            for (int j = 0; j < 4; j++) unpack2(Y2[ip][j], y[0][j], y[1][j]);
#pragma unroll
            for (int h = 0; h < 2; h++)
                *(float4*)(sm + SA + (nb + 2*ip + h) * 68 + db) =
                    make_float4(y[h][0]*0.125f, y[h][1]*0.125f,
                                y[h][2]*0.125f, y[h][3]*0.125f);
        }
        __syncthreads();   // WSM visible; all threads done reading buf
        if (p + 2 <= 4) stage_w64(buf, W4, 320, (p + 2) * 64, tid);  // overlap with scatter

        const float* wrow = sm + SA + e_loc * 68 + ch;
        if (p == 0) {
            float* dst = g_ms + r * 128 + ch;
#pragma unroll
            for (int g = 0; g < 4; g++) {
                float4 wv = *(const float4*)(wrow + g*4);
                float4 se = *(const float4*)(sep + g*4);
                red4v(dst + g*4, f4muls(f4mul(wv, se), sh0v));
            }
        } else if (p == 1) {
            float* dst = g_ms + r * 128 + 64 + ch;
#pragma unroll
            for (int g = 0; g < 4; g++) {
                float4 wv = *(const float4*)(wrow + g*4);
                float4 vx = *(const float4*)(vp + g*4);
                float4 vy = *(const float4*)(vp + 64 + g*4);
                float4 vz = *(const float4*)(vp + 128 + g*4);
                float4 dt = f4add(f4add(f4muls(vx, qx), f4muls(vy, qy)), f4muls(vz, qz));
                red4v(dst + g*4, f4muls(f4mul(wv, dt), i3));
            }
        } else if (p == 2) {
            float* dst = g_mv + r * 576 + ch * 3;
            float4 aqx = make_float4(qx,qx,qx,qx);
            float4 aqy = make_float4(qy,qy,qy,qy);
            float4 aqz = make_float4(qz,qz,qz,qz);
#pragma unroll
            for (int g = 0; g < 4; g++) {
                float4 wv = *(const float4*)(wrow + g*4);
                float4 se = *(const float4*)(sep + g*4);
                scatter_vec_group(dst + g*12, f4mul(wv, se), aqx, aqy, aqz);
            }
        } else if (p == 3) {
            float* dst = g_mv + r * 576 + 192 + ch * 3;
#pragma unroll
            for (int g = 0; g < 4; g++) {
                float4 wv = *(const float4*)(wrow + g*4);
                float4 vx = *(const float4*)(vp + g*4);
                float4 vy = *(const float4*)(vp + 64 + g*4);
                float4 vz = *(const float4*)(vp + 128 + g*4);
                scatter_vec_group(dst + g*12, f4muls(wv, sh0v), vx, vy, vz);
            }
        } else {
            float* dst = g_mv + r * 576 + 384 + ch * 3;
#pragma unroll
            for (int g = 0; g < 4; g++) {
                float4 wv = *(const float4*)(wrow + g*4);
                float4 vx = *(const float4*)(vp + g*4);
                float4 vy = *(const float4*)(vp + 64 + g*4);
                float4 vz = *(const float4*)(vp + 128 + g*4);
                float4 crx = f4sub(f4muls(vy, qz), f4muls(vz, qy));
                float4 cry = f4sub(f4muls(vz, qx), f4muls(vx, qz));
                float4 crz = f4sub(f4muls(vx, qy), f4muls(vy, qx));
                scatter_vec_group(dst + g*12, f4muls(wv, i2), crx, cry, crz);
            }
        }
    }
}

// ===================== K3: output linear (logic unchanged) =====================
#define K3_SMEM_BYTES (25344 * 4)
__global__ void __launch_bounds__(256, 2) out_kernel(
    const float* __restrict__ Wouts, const float* __restrict__ Woutv,
    float* __restrict__ out) {
    extern __shared__ float sm[];
    float* msm = sm;
    float* wbuf = sm + 13056;
    const int tid = threadIdx.x;
    const int n0 = blockIdx.x * 64;
    const int tx = tid & 15, ty = tid >> 4;
    const int nb = ty * 4, db = tx * 4;
    u64 Y2[2][4];

    for (int idx = tid; idx < 8192; idx += 256) {
        int n = idx >> 7, k = idx & 127, gn = n0 + n;
        msm[k * 68 + n] = (gn < NNODES) ? g_ms[gn * 128 + k] : 0.0f;
    }
    for (int idx = tid; idx < 8192; idx += 256) wbuf[idx] = Wouts[idx];
    __syncthreads();
    gemm_tile2<128, 68>(msm + nb, wbuf + db, Y2);
    const float ss = rsqrtf(128.0f) / 16.0f;
#pragma unroll
    for (int ip = 0; ip < 2; ip++) {
        float y[2][4];
#pragma unroll
        for (int j = 0; j < 4; j++) unpack2(Y2[ip][j], y[0][j], y[1][j]);
#pragma unroll
        for (int h = 0; h < 2; h++) {
            int gn = n0 + nb + 2*ip + h;
            if (gn < NNODES)
                *(float4*)(out + gn * 64 + db) =
                    make_float4(y[h][0]*ss, y[h][1]*ss, y[h][2]*ss, y[h][3]*ss);
        }
    }
    __syncthreads();
    for (int idx = tid; idx < 12288; idx += 256) wbuf[idx] = Woutv[idx];
    const float sv = rsqrtf(192.0f) / 16.0f;
#pragma unroll 1
    for (int x = 0; x < 3; x++) {
        __syncthreads();
        for (int idx = tid; idx < 12288; idx += 256) {
            int n = idx / 192, k = idx - n * 192, gn = n0 + n;
            msm[k * 68 + n] = (gn < NNODES) ? g_mv[gn * 576 + k * 3 + x] : 0.0f;
        }
        __syncthreads();
        gemm_tile2<192, 68>(msm + nb, wbuf + db, Y2);
#pragma unroll
        for (int ip = 0; ip < 2; ip++) {
            float y[2][4];
#pragma unroll
            for (int j = 0; j < 4; j++) unpack2(Y2[ip][j], y[0][j], y[1][j]);
#pragma unroll
            for (int h = 0; h < 2; h++) {
                int gn = n0 + nb + 2*ip + h;
                if (gn < NNODES)
#pragma unroll
                    for (int j = 0; j < 4; j++)
                        out[OUT_V_OFF + gn * 192 + (db + j) * 3 + x] = y[h][j] * sv;
            }
        }
    }
}

// ===================== launch =====================
extern "C" void kernel_launch(void* const* d_in, const int* in_sizes, int n_in,
                              void* d_out, int out_size) {
    const float* attrs = (const float*)d_in[0];
    const float* fs    = (const float*)d_in[1];
    const float* fv    = (const float*)d_in[2];
    const float* sh0   = (const float*)d_in[3];
    const float* sh1   = (const float*)d_in[4];
    const float* ef    = (const float*)d_in[5];
    const int*   snd   = (const int*)d_in[6];
    const int*   rcv   = (const int*)d_in[7];
    const float* Wscs  = (const float*)d_in[8];
    const float* Wscv  = (const float*)d_in[9];
    const float* Wses  = (const float*)d_in[10];
    const float* Wsev  = (const float*)d_in[11];
    const float* W1    = (const float*)d_in[12];
    const float* W2    = (const float*)d_in[13];
    const float* W3    = (const float*)d_in[14];
    const float* W4    = (const float*)d_in[15];
    const float* Wouts = (const float*)d_in[16];
    const float* Woutv = (const float*)d_in[17];
    float* out = (float*)d_out;

    cudaFuncSetAttribute(node_kernel, cudaFuncAttributeMaxDynamicSharedMemorySize, K1_SMEM_BYTES);
    cudaFuncSetAttribute(edge_kernel, cudaFuncAttributeMaxDynamicSharedMemorySize, K2_SMEM_BYTES);
    cudaFuncSetAttribute(out_kernel,  cudaFuncAttributeMaxDynamicSharedMemorySize, K3_SMEM_BYTES);

    zero_kernel<<<1024, 256>>>();
    node_kernel<<<(NNODES + 63) / 64, 256, K1_SMEM_BYTES>>>(
        attrs, fs, fv, Wscs, Wscv, Wses, Wsev, out);
    edge_kernel<<<NEDGES / 128, 512, K2_SMEM_BYTES>>>(
        ef, sh0, sh1, snd, rcv, W1, W2, W3, W4);
    out_kernel<<<(NNODES + 63) / 64, 256, K3_SMEM_BYTES>>>(Wouts, Woutv, out);
}

// round 12
// speedup vs baseline: 1.7021x; 1.0072x over previous
#include <cuda_runtime.h>

#define NNODES 50000
#define NEDGES 320000
#define OUT_V_OFF 3200000
#define SC_S_OFF  12800000
#define SC_V_OFF  16000000

typedef unsigned long long u64;

// ---- scratch (__device__ globals: allocation-free) ----
__device__ float g_s_scr[NNODES * 64];
__device__ float g_v_scr[NNODES * 192];   // [n][x][c]
__device__ float g_ms[NNODES * 128];      // [n][2C]
__device__ float g_mv[NNODES * 576];      // [n][3C][3]  (x innermost)

__device__ __forceinline__ float silu_f(float x) { return x / (1.0f + __expf(-x)); }

// ---- packed fp32x2 primitives ----
__device__ __forceinline__ u64 pack2(float lo, float hi) {
    u64 r; asm("mov.b64 %0, {%1, %2};" : "=l"(r) : "f"(lo), "f"(hi)); return r;
}
__device__ __forceinline__ u64 fma2(u64 a, u64 b, u64 c) {
    u64 d; asm("fma.rn.f32x2 %0, %1, %2, %3;" : "=l"(d) : "l"(a), "l"(b), "l"(c)); return d;
}
__device__ __forceinline__ void unpack2(u64 v, float& lo, float& hi) {
    asm("mov.b64 {%0, %1}, %2;" : "=f"(lo), "=f"(hi) : "l"(v));
}

// vectorized f32 reduction (sm_90+): one 16B L2 atomic op
__device__ __forceinline__ void red4v(float* p, float4 v) {
    asm volatile("red.global.add.v4.f32 [%0], {%1, %2, %3, %4};"
                 :: "l"(p), "f"(v.x), "f"(v.y), "f"(v.z), "f"(v.w) : "memory");
}

// ---- cp.async helpers ----
__device__ __forceinline__ unsigned smaddr(const void* p) {
    return (unsigned)__cvta_generic_to_shared(p);
}
__device__ __forceinline__ void cp16(unsigned dst, const float* src) {
    asm volatile("cp.async.cg.shared.global [%0], [%1], 16;" :: "r"(dst), "l"(src) : "memory");
}
__device__ __forceinline__ void cp_commit() {
    asm volatile("cp.async.commit_group;" ::: "memory");
}

__device__ __forceinline__ float4 f4mul(float4 a, float4 b) {
    return make_float4(a.x*b.x, a.y*b.y, a.z*b.z, a.w*b.w);
}
__device__ __forceinline__ float4 f4muls(float4 a, float s) {
    return make_float4(a.x*s, a.y*s, a.z*s, a.w*s);
}
__device__ __forceinline__ float4 f4sub(float4 a, float4 b) {
    return make_float4(a.x-b.x, a.y-b.y, a.z-b.z, a.w-b.w);
}
__device__ __forceinline__ float4 f4add(float4 a, float4 b) {
    return make_float4(a.x+b.x, a.y+b.y, a.z+b.z, a.w+b.w);
}

// interleaved vector-path scatter: 12 contiguous floats [4ch x 3xyz] = 3 v4 reds.
__device__ __forceinline__ void scatter_vec_group(float* dst, float4 val,
                                                  float4 ax, float4 ay, float4 az) {
    red4v(dst + 0, make_float4(val.x*ax.x, val.x*ay.x, val.x*az.x, val.y*ax.y));
    red4v(dst + 4, make_float4(val.y*ay.y, val.y*az.y, val.z*ax.z, val.z*ay.z));
    red4v(dst + 8, make_float4(val.z*az.z, val.w*ax.w, val.w*ay.w, val.w*az.w));
}

// 4-row x 4-col register-tile GEMM using packed fp32x2.
// A: [K][LDA] row(edge/node)-contig padded, W: [K][64].
template <int K, int LDA>
__device__ __forceinline__ void gemm_tile2(const float* __restrict__ A,
                                           const float* __restrict__ W,
                                           u64 Y2[2][4]) {
#pragma unroll
    for (int ip = 0; ip < 2; ip++)
#pragma unroll
        for (int j = 0; j < 4; j++) Y2[ip][j] = 0ull;
#pragma unroll 8
    for (int c = 0; c < K; c++) {
        ulonglong2 a2 = *(const ulonglong2*)(A + c * LDA);
        float4 w = *(const float4*)(W + c * 64);
        u64 w0 = pack2(w.x, w.x), w1 = pack2(w.y, w.y);
        u64 w2 = pack2(w.z, w.z), w3 = pack2(w.w, w.w);
        Y2[0][0] = fma2(a2.x, w0, Y2[0][0]);
        Y2[0][1] = fma2(a2.x, w1, Y2[0][1]);
        Y2[0][2] = fma2(a2.x, w2, Y2[0][2]);
        Y2[0][3] = fma2(a2.x, w3, Y2[0][3]);
        Y2[1][0] = fma2(a2.y, w0, Y2[1][0]);
        Y2[1][1] = fma2(a2.y, w1, Y2[1][1]);
        Y2[1][2] = fma2(a2.y, w2, Y2[1][2]);
        Y2[1][3] = fma2(a2.y, w3, Y2[1][3]);
    }
}

// ===================== K0: zero scratch =====================
__global__ void zero_kernel() {
    long i = (long)blockIdx.x * blockDim.x + threadIdx.x;
    long t = (long)gridDim.x * blockDim.x;
    float4 z = make_float4(0.f, 0.f, 0.f, 0.f);
    for (long j = i; j < (long)NNODES * 128 / 4; j += t) ((float4*)g_ms)[j] = z;
    for (long j = i; j < (long)NNODES * 576 / 4; j += t) ((float4*)g_mv)[j] = z;
}

// ===================== K1: node side — 128-node tiles + cp.async panels ====
// 512 threads, grid 391. smem (floats):
//   fsm @0     : [64][132] = 8448
//   fvm @8448  : 3 x [64][132] = 25344
//   WB0 @33792 : 4096   (weight panel buf 0)
//   WB1 @37888 : 4096   (weight panel buf 1)
//   atm @41984 : [128][10] = 1280
// total 43264 floats = 173 KB -> 1 CTA/SM, 16 warps
#define NLDA 132
#define NFSM 0
#define NFVM 8448
#define NWB0 33792
#define NWB1 37888
#define NATM 41984
#define K1_SMEM_BYTES (43264 * 4)
#define NTILE 128

// stage one 64x64 panel (rows stride ld_src) via cp.async; one commit group.
__device__ __forceinline__ void stage_panel(float* dst, const float* src,
                                            int ld_src, int tid) {
#pragma unroll
    for (int i = tid; i < 1024; i += 512) {
        int k = i >> 4, c4 = (i & 15) * 4;
        cp16(smaddr(dst + k * 64 + c4), src + k * ld_src + c4);
    }
    cp_commit();
}

__global__ void __launch_bounds__(512, 1) node_kernel(
    const float* __restrict__ attrs_g, const float* __restrict__ fs_g,
    const float* __restrict__ fv_g,
    const float* __restrict__ Wscs, const float* __restrict__ Wscv,
    const float* __restrict__ Wses, const float* __restrict__ Wsev,
    float* __restrict__ out) {
    extern __shared__ float sm[];
    const int tid = threadIdx.x;
    const int n0 = blockIdx.x * NTILE;
    const int tx = tid & 15, ty = tid >> 4;    // ty 0..31
    const int nb = ty * 4, db = tx * 4;

    // ---- panel source table (22 panels) ----
    // p<10: Wscs+p*64 (ld 640); p<20: Wscv+(p-10)*64 (ld 640); 20: Wses; 21: Wsev
    // prologue: stage panels 0,1
    stage_panel(sm + NWB0, Wscs + 0 * 64, 640, tid);
    stage_panel(sm + NWB1, Wscs + 1 * 64, 640, tid);

    // ---- stage activations ----
    for (int idx = tid; idx < NTILE * 64; idx += 512) {
        int n = idx >> 6, c = idx & 63, gn = n0 + n;
        sm[NFSM + c * NLDA + n] = (gn < NNODES) ? fs_g[gn * 64 + c] : 0.0f;
    }
    for (int idx = tid; idx < NTILE * 192; idx += 512) {
        int n = idx / 192, r = idx - n * 192, c = r / 3, x = r - c * 3, gn = n0 + n;
        sm[NFVM + x * 8448 + c * NLDA + n] = (gn < NNODES) ? fv_g[gn * 192 + r] : 0.0f;
    }
    for (int idx = tid; idx < NTILE * 10; idx += 512) {
        int n = idx / 10, gn = n0 + n;
        sm[NATM + idx] = (gn < NNODES) ? attrs_g[gn * 10 + (idx - n * 10)] : 0.0f;
    }

    u64 acc_s[2][4], acc_v[3][2][4], Y2[2][4];
#pragma unroll
    for (int ip = 0; ip < 2; ip++)
#pragma unroll
        for (int j = 0; j < 4; j++) acc_s[ip][j] = 0ull;
#pragma unroll
    for (int x = 0; x < 3; x++)
#pragma unroll
        for (int ip = 0; ip < 2; ip++)
#pragma unroll
            for (int j = 0; j < 4; j++) acc_v[x][ip][j] = 0ull;

    const float isc = rsqrtf(640.0f);

#pragma unroll 1
    for (int p = 0; p < 22; p++) {
        if (p == 21) asm volatile("cp.async.wait_group 0;" ::: "memory");
        else         asm volatile("cp.async.wait_group 1;" ::: "memory");
        __syncthreads();   // panel p visible; prior readers of this buffer done
        const float* WB = sm + ((p & 1) ? NWB1 : NWB0);

        if (p < 10) {
            // scalar skip-TP, attr index a = p
            gemm_tile2<64, NLDA>(sm + NFSM + nb, WB + db, Y2);
#pragma unroll
            for (int ip = 0; ip < 2; ip++) {
                u64 av2 = pack2(sm[NATM + (nb + 2*ip) * 10 + p],
                                sm[NATM + (nb + 2*ip + 1) * 10 + p]);
#pragma unroll
                for (int j = 0; j < 4; j++) acc_s[ip][j] = fma2(av2, Y2[ip][j], acc_s[ip][j]);
            }
        } else if (p < 20) {
            const int a = p - 10;
#pragma unroll 1
            for (int x = 0; x < 3; x++) {
                gemm_tile2<64, NLDA>(sm + NFVM + x * 8448 + nb, WB + db, Y2);
#pragma unroll
                for (int ip = 0; ip < 2; ip++) {
                    u64 av2 = pack2(sm[NATM + (nb + 2*ip) * 10 + a],
                                    sm[NATM + (nb + 2*ip + 1) * 10 + a]);
#pragma unroll
                    for (int j = 0; j < 4; j++) acc_v[x][ip][j] = fma2(av2, Y2[ip][j], acc_v[x][ip][j]);
                }
            }
        } else if (p == 20) {
            // self linear scalar -> g_s_scr
            gemm_tile2<64, NLDA>(sm + NFSM + nb, WB + db, Y2);
#pragma unroll
            for (int ip = 0; ip < 2; ip++) {
                float y[2][4];
#pragma unroll
                for (int j = 0; j < 4; j++) unpack2(Y2[ip][j], y[0][j], y[1][j]);
#pragma unroll
                for (int h = 0; h < 2; h++) {
                    int gn = n0 + nb + 2*ip + h;
                    if (gn < NNODES)
                        *(float4*)(g_s_scr + gn * 64 + db) =
                            make_float4(y[h][0]*0.125f, y[h][1]*0.125f,
                                        y[h][2]*0.125f, y[h][3]*0.125f);
                }
            }
        } else {
            // self linear vector -> g_v_scr
#pragma unroll 1
            for (int x = 0; x < 3; x++) {
                gemm_tile2<64, NLDA>(sm + NFVM + x * 8448 + nb, WB + db, Y2);
#pragma unroll
                for (int ip = 0; ip < 2; ip++) {
                    float y[2][4];
#pragma unroll
                    for (int j = 0; j < 4; j++) unpack2(Y2[ip][j], y[0][j], y[1][j]);
#pragma unroll
                    for (int h = 0; h < 2; h++) {
                        int gn = n0 + nb + 2*ip + h;
                        if (gn < NNODES)
                            *(float4*)(g_v_scr + gn * 192 + x * 64 + db) =
                                make_float4(y[h][0]*0.125f, y[h][1]*0.125f,
                                            y[h][2]*0.125f, y[h][3]*0.125f);
                    }
                }
            }
        }
        __syncthreads();   // all threads done reading this buffer
        // stage panel p+2 into the buffer just freed
        if (p + 2 < 22) {
            float* dst = sm + ((p & 1) ? NWB1 : NWB0);
            int q = p + 2;
            const float* src = (q < 10) ? (Wscs + q * 64)
                             : (q < 20) ? (Wscv + (q - 10) * 64)
                             : (q == 20) ? Wses : Wsev;
            int ld = (q < 20) ? 640 : 64;
            stage_panel(dst, src, ld, tid);
        }
    }

    // ---- skip-connection outputs ----
#pragma unroll
    for (int ip = 0; ip < 2; ip++) {
        float ys[2][4], yv[3][2][4];
#pragma unroll
        for (int j = 0; j < 4; j++) {
            unpack2(acc_s[ip][j], ys[0][j], ys[1][j]);
#pragma unroll
            for (int x = 0; x < 3; x++) unpack2(acc_v[x][ip][j], yv[x][0][j], yv[x][1][j]);
        }
#pragma unroll
        for (int h = 0; h < 2; h++) {
            int gn = n0 + nb + 2*ip + h;
            if (gn < NNODES) {
                *(float4*)(out + SC_S_OFF + gn * 64 + db) =
                    make_float4(ys[h][0]*isc, ys[h][1]*isc, ys[h][2]*isc, ys[h][3]*isc);
#pragma unroll
                for (int j = 0; j < 4; j++)
#pragma unroll
                    for (int x = 0; x < 3; x++)
                        out[SC_V_OFF + (gn * 64 + db + j) * 3 + x] = yv[x][h][j] * isc;
            }
        }
    }
}

// ===================== K2: edge side — unchanged from R11 =====================
#define SA 0
#define SB 8960
#define SW1 17920
#define WS0 18432
#define WS1 22528
#define SMETA 26624
#define K2_SMEM_BYTES (27392 * 4)

__device__ __forceinline__ void store_actT(float* dst, const u64 Y2[2][4],
                                           int nb, int db, float scale) {
#pragma unroll
    for (int ip = 0; ip < 2; ip++)
#pragma unroll
        for (int j = 0; j < 4; j++) {
            float lo, hi; unpack2(Y2[ip][j], lo, hi);
            *(float2*)(dst + (db + j) * 140 + nb + 2*ip) =
                make_float2(silu_f(lo * scale), silu_f(hi * scale));
        }
}

__device__ __forceinline__ void stage_w64(float* dst, const float* src,
                                          int ld_src, int col0, int tid) {
#pragma unroll
    for (int i = tid; i < 1024; i += 512) {
        int k = i >> 4, c4 = (i & 15) * 4;
        cp16(smaddr(dst + k * 64 + c4), src + k * ld_src + col0 + c4);
    }
    cp_commit();
}

__global__ void __launch_bounds__(512, 2) edge_kernel(
    const float* __restrict__ ef_g, const float* __restrict__ sh0_g,
    const float* __restrict__ sh1_g, const int* __restrict__ snd_g,
    const int* __restrict__ rcv_g,
    const float* __restrict__ W1, const float* __restrict__ W2,
    const float* __restrict__ W3, const float* __restrict__ W4) {
    extern __shared__ float sm[];
    const int tid = threadIdx.x;
    const int e0 = blockIdx.x * 128;
    const int tx = tid & 15, ty = tid >> 4;
    const int nb = ty * 4, db = tx * 4;
    const int e_loc = tid >> 2, cg = tid & 3, ch = cg * 16;
    const float i3 = rsqrtf(3.0f), i2 = rsqrtf(2.0f), is8 = rsqrtf(8.0f);
    u64 Y2[2][4];

    if (tid < 128) {
        int ge = e0 + tid;
        ((int*)(sm + SMETA))[tid]       = snd_g[ge];
        ((int*)(sm + SMETA + 128))[tid] = rcv_g[ge];
        sm[SMETA + 256 + tid] = sh0_g[ge];
        sm[SMETA + 384 + tid] = sh1_g[ge * 3 + 0];
        sm[SMETA + 512 + tid] = sh1_g[ge * 3 + 1];
        sm[SMETA + 640 + tid] = sh1_g[ge * 3 + 2];
    }
    for (int i = tid; i < 1024; i += 512) {
        int e = i >> 3, k = i & 7;
        sm[SA + k * 140 + e] = ef_g[e0 * 8 + i];
    }
    sm[SW1 + tid] = W1[tid];
    stage_w64(sm + WS0, W2, 64, 0, tid);
    stage_w64(sm + WS1, W3, 64, 0, tid);
    __syncthreads();

    gemm_tile2<8, 140>(sm + SA + nb, sm + SW1 + db, Y2);
    store_actT(sm + SB, Y2, nb, db, is8);
    asm volatile("cp.async.wait_group 1;" ::: "memory");
    __syncthreads();

    gemm_tile2<64, 140>(sm + SB + nb, sm + WS0 + db, Y2);
    store_actT(sm + SA, Y2, nb, db, 0.125f);
    asm volatile("cp.async.wait_group 0;" ::: "memory");
    __syncthreads();
    stage_w64(sm + WS0, W4, 320, 0 * 64, tid);

    gemm_tile2<64, 140>(sm + SA + nb, sm + WS1 + db, Y2);
    store_actT(sm + SB, Y2, nb, db, 0.125f);
    __syncthreads();
    stage_w64(sm + WS1, W4, 320, 1 * 64, tid);

    const int s = ((const int*)(sm + SMETA))[e_loc];
    const int r = ((const int*)(sm + SMETA + 128))[e_loc];
    const float sh0v = sm[SMETA + 256 + e_loc];
    const float qx = sm[SMETA + 384 + e_loc];
    const float qy = sm[SMETA + 512 + e_loc];
    const float qz = sm[SMETA + 640 + e_loc];
    const float* sep = g_s_scr + s * 64 + ch;
    const float* vp  = g_v_scr + s * 192 + ch;

#pragma unroll 1
    for (int p = 0; p < 5; p++) {
        float* buf = sm + ((p & 1) ? WS1 : WS0);
        if (p < 4) asm volatile("cp.async.wait_group 1;" ::: "memory");
        else       asm volatile("cp.async.wait_group 0;" ::: "memory");
        __syncthreads();

        gemm_tile2<64, 140>(sm + SB + nb, buf + db, Y2);
#pragma unroll
        for (int ip = 0; ip < 2; ip++) {
            float y[2][4];
#pragma unroll
            for (int j = 0; j < 4; j++) unpack2(Y2[ip][j], y[0][j], y[1][j]);
#pragma unroll
            for (int h = 0; h < 2; h++)
                *(float4*)(sm + SA + (nb + 2*ip + h) * 68 + db) =
                    make_float4(y[h][0]*0.125f, y[h][1]*0.125f,
                                y[h][2]*0.125f, y[h][3]*0.125f);
        }
        __syncthreads();
        if (p + 2 <= 4) stage_w64(buf, W4, 320, (p + 2) * 64, tid);

        const float* wrow = sm + SA + e_loc * 68 + ch;
        if (p == 0) {
            float* dst = g_ms + r * 128 + ch;
#pragma unroll
            for (int g = 0; g < 4; g++) {
                float4 wv = *(const float4*)(wrow + g*4);
                float4 se = *(const float4*)(sep + g*4);
                red4v(dst + g*4, f4muls(f4mul(wv, se), sh0v));
            }
        } else if (p == 1) {
            float* dst = g_ms + r * 128 + 64 + ch;
#pragma unroll
            for (int g = 0; g < 4; g++) {
                float4 wv = *(const float4*)(wrow + g*4);
                float4 vx = *(const float4*)(vp + g*4);
                float4 vy = *(const float4*)(vp + 64 + g*4);
                float4 vz = *(const float4*)(vp + 128 + g*4);
                float4 dt = f4add(f4add(f4muls(vx, qx), f4muls(vy, qy)), f4muls(vz, qz));
                red4v(dst + g*4, f4muls(f4mul(wv, dt), i3));
            }
        } else if (p == 2) {
            float* dst = g_mv + r * 576 + ch * 3;
            float4 aqx = make_float4(qx,qx,qx,qx);
            float4 aqy = make_float4(qy,qy,qy,qy);
            float4 aqz = make_float4(qz,qz,qz,qz);
#pragma unroll
            for (int g = 0; g < 4; g++) {
                float4 wv = *(const float4*)(wrow + g*4);
                float4 se = *(const float4*)(sep + g*4);
                scatter_vec_group(dst + g*12, f4mul(wv, se), aqx, aqy, aqz);
            }
        } else if (p == 3) {
            float* dst = g_mv + r * 576 + 192 + ch * 3;
#pragma unroll
            for (int g = 0; g < 4; g++) {
                float4 wv = *(const float4*)(wrow + g*4);
                float4 vx = *(const float4*)(vp + g*4);
                float4 vy = *(const float4*)(vp + 64 + g*4);
                float4 vz = *(const float4*)(vp + 128 + g*4);
                scatter_vec_group(dst + g*12, f4muls(wv, sh0v), vx, vy, vz);
            }
        } else {
            float* dst = g_mv + r * 576 + 384 + ch * 3;
#pragma unroll
            for (int g = 0; g < 4; g++) {
                float4 wv = *(const float4*)(wrow + g*4);
                float4 vx = *(const float4*)(vp + g*4);
                float4 vy = *(const float4*)(vp + 64 + g*4);
                float4 vz = *(const float4*)(vp + 128 + g*4);
                float4 crx = f4sub(f4muls(vy, qz), f4muls(vz, qy));
                float4 cry = f4sub(f4muls(vz, qx), f4muls(vx, qz));
                float4 crz = f4sub(f4muls(vx, qy), f4muls(vy, qx));
                scatter_vec_group(dst + g*12, f4muls(wv, i2), crx, cry, crz);
            }
        }
    }
}

// ===================== K3: output linear (unchanged) =====================
#define K3_SMEM_BYTES (25344 * 4)
__global__ void __launch_bounds__(256, 2) out_kernel(
    const float* __restrict__ Wouts, const float* __restrict__ Woutv,
    float* __restrict__ out) {
    extern __shared__ float sm[];
    float* msm = sm;
    float* wbuf = sm + 13056;
    const int tid = threadIdx.x;
    const int n0 = blockIdx.x * 64;
    const int tx = tid & 15, ty = tid >> 4;
    const int nb = ty * 4, db = tx * 4;
    u64 Y2[2][4];

    for (int idx = tid; idx < 8192; idx += 256) {
        int n = idx >> 7, k = idx & 127, gn = n0 + n;
        msm[k * 68 + n] = (gn < NNODES) ? g_ms[gn * 128 + k] : 0.0f;
    }
    for (int idx = tid; idx < 8192; idx += 256) wbuf[idx] = Wouts[idx];
    __syncthreads();
    gemm_tile2<128, 68>(msm + nb, wbuf + db, Y2);
    const float ss = rsqrtf(128.0f) / 16.0f;
#pragma unroll
    for (int ip = 0; ip < 2; ip++) {
        float y[2][4];
#pragma unroll
        for (int j = 0; j < 4; j++) unpack2(Y2[ip][j], y[0][j], y[1][j]);
#pragma unroll
        for (int h = 0; h < 2; h++) {
            int gn = n0 + nb + 2*ip + h;
            if (gn < NNODES)
                *(float4*)(out + gn * 64 + db) =
                    make_float4(y[h][0]*ss, y[h][1]*ss, y[h][2]*ss, y[h][3]*ss);
        }
    }
    __syncthreads();
    for (int idx = tid; idx < 12288; idx += 256) wbuf[idx] = Woutv[idx];
    const float sv = rsqrtf(192.0f) / 16.0f;
#pragma unroll 1
    for (int x = 0; x < 3; x++) {
        __syncthreads();
        for (int idx = tid; idx < 12288; idx += 256) {
            int n = idx / 192, k = idx - n * 192, gn = n0 + n;
            msm[k * 68 + n] = (gn < NNODES) ? g_mv[gn * 576 + k * 3 + x] : 0.0f;
        }
        __syncthreads();
        gemm_tile2<192, 68>(msm + nb, wbuf + db, Y2);
#pragma unroll
        for (int ip = 0; ip < 2; ip++) {
            float y[2][4];
#pragma unroll
            for (int j = 0; j < 4; j++) unpack2(Y2[ip][j], y[0][j], y[1][j]);
#pragma unroll
            for (int h = 0; h < 2; h++) {
                int gn = n0 + nb + 2*ip + h;
                if (gn < NNODES)
#pragma unroll
                    for (int j = 0; j < 4; j++)
                        out[OUT_V_OFF + gn * 192 + (db + j) * 3 + x] = y[h][j] * sv;
            }
        }
    }
}

// ===================== launch =====================
extern "C" void kernel_launch(void* const* d_in, const int* in_sizes, int n_in,
                              void* d_out, int out_size) {
    const float* attrs = (const float*)d_in[0];
    const float* fs    = (const float*)d_in[1];
    const float* fv    = (const float*)d_in[2];
    const float* sh0   = (const float*)d_in[3];
    const float* sh1   = (const float*)d_in[4];
    const float* ef    = (const float*)d_in[5];
    const int*   snd   = (const int*)d_in[6];
    const int*   rcv   = (const int*)d_in[7];
    const float* Wscs  = (const float*)d_in[8];
    const float* Wscv  = (const float*)d_in[9];
    const float* Wses  = (const float*)d_in[10];
    const float* Wsev  = (const float*)d_in[11];
    const float* W1    = (const float*)d_in[12];
    const float* W2    = (const float*)d_in[13];
    const float* W3    = (const float*)d_in[14];
    const float* W4    = (const float*)d_in[15];
    const float* Wouts = (const float*)d_in[16];
    const float* Woutv = (const float*)d_in[17];
    float* out = (float*)d_out;

    cudaFuncSetAttribute(node_kernel, cudaFuncAttributeMaxDynamicSharedMemorySize, K1_SMEM_BYTES);
    cudaFuncSetAttribute(edge_kernel, cudaFuncAttributeMaxDynamicSharedMemorySize, K2_SMEM_BYTES);
    cudaFuncSetAttribute(out_kernel,  cudaFuncAttributeMaxDynamicSharedMemorySize, K3_SMEM_BYTES);

    zero_kernel<<<1024, 256>>>();
    node_kernel<<<(NNODES + NTILE - 1) / NTILE, 512, K1_SMEM_BYTES>>>(
        attrs, fs, fv, Wscs, Wscv, Wses, Wsev, out);
    edge_kernel<<<NEDGES / 128, 512, K2_SMEM_BYTES>>>(
        ef, sh0, sh1, snd, rcv, W1, W2, W3, W4);
    out_kernel<<<(NNODES + 63) / 64, 256, K3_SMEM_BYTES>>>(Wouts, Woutv, out);
}

// round 13
// speedup vs baseline: 1.7206x; 1.0108x over previous
#include <cuda_runtime.h>

#define NNODES 50000
#define NEDGES 320000
#define OUT_V_OFF 3200000
#define SC_S_OFF  12800000
#define SC_V_OFF  16000000

typedef unsigned long long u64;

// ---- scratch (__device__ globals: allocation-free) ----
__device__ float g_s_scr[NNODES * 64];
__device__ float g_v_scr[NNODES * 192];   // [n][x][c]
__device__ float g_ms[NNODES * 128];      // [n][2C]
__device__ float g_mv[NNODES * 576];      // [n][3C][3]  (x innermost)

__device__ __forceinline__ float silu_f(float x) { return x / (1.0f + __expf(-x)); }

// ---- packed fp32x2 primitives ----
__device__ __forceinline__ u64 pack2(float lo, float hi) {
    u64 r; asm("mov.b64 %0, {%1, %2};" : "=l"(r) : "f"(lo), "f"(hi)); return r;
}
__device__ __forceinline__ u64 fma2(u64 a, u64 b, u64 c) {
    u64 d; asm("fma.rn.f32x2 %0, %1, %2, %3;" : "=l"(d) : "l"(a), "l"(b), "l"(c)); return d;
}
__device__ __forceinline__ void unpack2(u64 v, float& lo, float& hi) {
    asm("mov.b64 {%0, %1}, %2;" : "=f"(lo), "=f"(hi) : "l"(v));
}

// vectorized f32 reduction (sm_90+): one 16B L2 atomic op
__device__ __forceinline__ void red4v(float* p, float4 v) {
    asm volatile("red.global.add.v4.f32 [%0], {%1, %2, %3, %4};"
                 :: "l"(p), "f"(v.x), "f"(v.y), "f"(v.z), "f"(v.w) : "memory");
}

// ---- cp.async helpers ----
__device__ __forceinline__ unsigned smaddr(const void* p) {
    return (unsigned)__cvta_generic_to_shared(p);
}
__device__ __forceinline__ void cp16(unsigned dst, const float* src) {
    asm volatile("cp.async.cg.shared.global [%0], [%1], 16;" :: "r"(dst), "l"(src) : "memory");
}
__device__ __forceinline__ void cp_commit() {
    asm volatile("cp.async.commit_group;" ::: "memory");
}

__device__ __forceinline__ float4 f4mul(float4 a, float4 b) {
    return make_float4(a.x*b.x, a.y*b.y, a.z*b.z, a.w*b.w);
}
__device__ __forceinline__ float4 f4muls(float4 a, float s) {
    return make_float4(a.x*s, a.y*s, a.z*s, a.w*s);
}
__device__ __forceinline__ float4 f4sub(float4 a, float4 b) {
    return make_float4(a.x-b.x, a.y-b.y, a.z-b.z, a.w-b.w);
}
__device__ __forceinline__ float4 f4add(float4 a, float4 b) {
    return make_float4(a.x+b.x, a.y+b.y, a.z+b.z, a.w+b.w);
}

// interleaved vector-path scatter: 12 contiguous floats [4ch x 3xyz] = 3 v4 reds.
__device__ __forceinline__ void scatter_vec_group(float* dst, float4 val,
                                                  float4 ax, float4 ay, float4 az) {
    red4v(dst + 0, make_float4(val.x*ax.x, val.x*ay.x, val.x*az.x, val.y*ax.y));
    red4v(dst + 4, make_float4(val.y*ay.y, val.y*az.y, val.z*ax.z, val.z*ay.z));
    red4v(dst + 8, make_float4(val.z*az.z, val.w*ax.w, val.w*ay.w, val.w*az.w));
}

// 8-row x 2-col register-tile GEMM using packed fp32x2.
// A: [K][LDA] row-contig padded (rows nb..nb+7 via 2 ulonglong2), W: [K][64].
// Y[rp][c]: row-pair (2rp, 2rp+1) packed lo/hi, c = column db+c.
// Per k-step: 3 LDS + 4 MOV + 8 FFMA2 (vs 18-issue 4x4 tile).
template <int K, int LDA>
__device__ __forceinline__ void gemm8x2(const float* __restrict__ A,
                                        const float* __restrict__ W,
                                        u64 Y[4][2]) {
#pragma unroll
    for (int rp = 0; rp < 4; rp++) { Y[rp][0] = 0ull; Y[rp][1] = 0ull; }
#pragma unroll 8
    for (int c = 0; c < K; c++) {
        ulonglong2 a01 = *(const ulonglong2*)(A + c * LDA);
        ulonglong2 a23 = *(const ulonglong2*)(A + c * LDA + 4);
        float2 w = *(const float2*)(W + c * 64);
        u64 w0 = pack2(w.x, w.x), w1 = pack2(w.y, w.y);
        Y[0][0] = fma2(a01.x, w0, Y[0][0]);
        Y[0][1] = fma2(a01.x, w1, Y[0][1]);
        Y[1][0] = fma2(a01.y, w0, Y[1][0]);
        Y[1][1] = fma2(a01.y, w1, Y[1][1]);
        Y[2][0] = fma2(a23.x, w0, Y[2][0]);
        Y[2][1] = fma2(a23.x, w1, Y[2][1]);
        Y[3][0] = fma2(a23.y, w0, Y[3][0]);
        Y[3][1] = fma2(a23.y, w1, Y[3][1]);
    }
}

// ===================== K0: zero scratch =====================
__global__ void zero_kernel() {
    long i = (long)blockIdx.x * blockDim.x + threadIdx.x;
    long t = (long)gridDim.x * blockDim.x;
    float4 z = make_float4(0.f, 0.f, 0.f, 0.f);
    for (long j = i; j < (long)NNODES * 128 / 4; j += t) ((float4*)g_ms)[j] = z;
    for (long j = i; j < (long)NNODES * 576 / 4; j += t) ((float4*)g_mv)[j] = z;
}

// ===================== K1: node side — 128-node tiles, 8x2 tiles ====
#define NLDA 132
#define NFSM 0
#define NFVM 8448
#define NWB0 33792
#define NWB1 37888
#define NATM 41984
#define K1_SMEM_BYTES (43264 * 4)
#define NTILE 128

__device__ __forceinline__ void stage_panel(float* dst, const float* src,
                                            int ld_src, int tid) {
#pragma unroll
    for (int i = tid; i < 1024; i += 512) {
        int k = i >> 4, c4 = (i & 15) * 4;
        cp16(smaddr(dst + k * 64 + c4), src + k * ld_src + c4);
    }
    cp_commit();
}

__global__ void __launch_bounds__(512, 1) node_kernel(
    const float* __restrict__ attrs_g, const float* __restrict__ fs_g,
    const float* __restrict__ fv_g,
    const float* __restrict__ Wscs, const float* __restrict__ Wscv,
    const float* __restrict__ Wses, const float* __restrict__ Wsev,
    float* __restrict__ out) {
    extern __shared__ float sm[];
    const int tid = threadIdx.x;
    const int n0 = blockIdx.x * NTILE;
    const int tx = tid & 31, ty = tid >> 5;    // ty 0..15 rows, tx 0..31 cols
    const int nb = ty * 8, db = tx * 2;

    stage_panel(sm + NWB0, Wscs + 0 * 64, 640, tid);
    stage_panel(sm + NWB1, Wscs + 1 * 64, 640, tid);

    for (int idx = tid; idx < NTILE * 64; idx += 512) {
        int n = idx >> 6, c = idx & 63, gn = n0 + n;
        sm[NFSM + c * NLDA + n] = (gn < NNODES) ? fs_g[gn * 64 + c] : 0.0f;
    }
    for (int idx = tid; idx < NTILE * 192; idx += 512) {
        int n = idx / 192, r = idx - n * 192, c = r / 3, x = r - c * 3, gn = n0 + n;
        sm[NFVM + x * 8448 + c * NLDA + n] = (gn < NNODES) ? fv_g[gn * 192 + r] : 0.0f;
    }
    for (int idx = tid; idx < NTILE * 10; idx += 512) {
        int n = idx / 10, gn = n0 + n;
        sm[NATM + idx] = (gn < NNODES) ? attrs_g[gn * 10 + (idx - n * 10)] : 0.0f;
    }

    u64 acc_s[4][2], acc_v[3][4][2], Y[4][2];
#pragma unroll
    for (int rp = 0; rp < 4; rp++) { acc_s[rp][0] = 0ull; acc_s[rp][1] = 0ull; }
#pragma unroll
    for (int x = 0; x < 3; x++)
#pragma unroll
        for (int rp = 0; rp < 4; rp++) { acc_v[x][rp][0] = 0ull; acc_v[x][rp][1] = 0ull; }

    const float isc = rsqrtf(640.0f);

#pragma unroll 1
    for (int p = 0; p < 22; p++) {
        if (p == 21) asm volatile("cp.async.wait_group 0;" ::: "memory");
        else         asm volatile("cp.async.wait_group 1;" ::: "memory");
        __syncthreads();
        const float* WB = sm + ((p & 1) ? NWB1 : NWB0);

        if (p < 10) {
            gemm8x2<64, NLDA>(sm + NFSM + nb, WB + db, Y);
#pragma unroll
            for (int rp = 0; rp < 4; rp++) {
                u64 av2 = pack2(sm[NATM + (nb + 2*rp) * 10 + p],
                                sm[NATM + (nb + 2*rp + 1) * 10 + p]);
                acc_s[rp][0] = fma2(av2, Y[rp][0], acc_s[rp][0]);
                acc_s[rp][1] = fma2(av2, Y[rp][1], acc_s[rp][1]);
            }
        } else if (p < 20) {
            const int a = p - 10;
#pragma unroll 1
            for (int x = 0; x < 3; x++) {
                gemm8x2<64, NLDA>(sm + NFVM + x * 8448 + nb, WB + db, Y);
#pragma unroll
                for (int rp = 0; rp < 4; rp++) {
                    u64 av2 = pack2(sm[NATM + (nb + 2*rp) * 10 + a],
                                    sm[NATM + (nb + 2*rp + 1) * 10 + a]);
                    acc_v[x][rp][0] = fma2(av2, Y[rp][0], acc_v[x][rp][0]);
                    acc_v[x][rp][1] = fma2(av2, Y[rp][1], acc_v[x][rp][1]);
                }
            }
        } else if (p == 20) {
            gemm8x2<64, NLDA>(sm + NFSM + nb, WB + db, Y);
#pragma unroll
            for (int rp = 0; rp < 4; rp++) {
                float y0l, y0h, y1l, y1h;
                unpack2(Y[rp][0], y0l, y0h);
                unpack2(Y[rp][1], y1l, y1h);
                int gn0 = n0 + nb + 2*rp;
                if (gn0 < NNODES)
                    *(float2*)(g_s_scr + gn0 * 64 + db) = make_float2(y0l*0.125f, y1l*0.125f);
                if (gn0 + 1 < NNODES)
                    *(float2*)(g_s_scr + (gn0+1) * 64 + db) = make_float2(y0h*0.125f, y1h*0.125f);
            }
        } else {
#pragma unroll 1
            for (int x = 0; x < 3; x++) {
                gemm8x2<64, NLDA>(sm + NFVM + x * 8448 + nb, WB + db, Y);
#pragma unroll
                for (int rp = 0; rp < 4; rp++) {
                    float y0l, y0h, y1l, y1h;
                    unpack2(Y[rp][0], y0l, y0h);
                    unpack2(Y[rp][1], y1l, y1h);
                    int gn0 = n0 + nb + 2*rp;
                    if (gn0 < NNODES)
                        *(float2*)(g_v_scr + gn0 * 192 + x * 64 + db) =
                            make_float2(y0l*0.125f, y1l*0.125f);
                    if (gn0 + 1 < NNODES)
                        *(float2*)(g_v_scr + (gn0+1) * 192 + x * 64 + db) =
                            make_float2(y0h*0.125f, y1h*0.125f);
                }
            }
        }
        __syncthreads();
        if (p + 2 < 22) {
            float* dst = sm + ((p & 1) ? NWB1 : NWB0);
            int q = p + 2;
            const float* src = (q < 10) ? (Wscs + q * 64)
                             : (q < 20) ? (Wscv + (q - 10) * 64)
                             : (q == 20) ? Wses : Wsev;
            int ld = (q < 20) ? 640 : 64;
            stage_panel(dst, src, ld, tid);
        }
    }

    // ---- skip-connection outputs ----
#pragma unroll
    for (int rp = 0; rp < 4; rp++) {
        float s0l, s0h, s1l, s1h;
        unpack2(acc_s[rp][0], s0l, s0h);
        unpack2(acc_s[rp][1], s1l, s1h);
        float v0l[3], v0h[3], v1l[3], v1h[3];
#pragma unroll
        for (int x = 0; x < 3; x++) {
            unpack2(acc_v[x][rp][0], v0l[x], v0h[x]);
            unpack2(acc_v[x][rp][1], v1l[x], v1h[x]);
        }
        int gn0 = n0 + nb + 2*rp;
        if (gn0 < NNODES) {
            *(float2*)(out + SC_S_OFF + gn0 * 64 + db) = make_float2(s0l*isc, s1l*isc);
#pragma unroll
            for (int x = 0; x < 3; x++) {
                out[SC_V_OFF + (gn0 * 64 + db) * 3 + x]     = v0l[x] * isc;
                out[SC_V_OFF + (gn0 * 64 + db + 1) * 3 + x] = v1l[x] * isc;
            }
        }
        if (gn0 + 1 < NNODES) {
            *(float2*)(out + SC_S_OFF + (gn0+1) * 64 + db) = make_float2(s0h*isc, s1h*isc);
#pragma unroll
            for (int x = 0; x < 3; x++) {
                out[SC_V_OFF + ((gn0+1) * 64 + db) * 3 + x]     = v0h[x] * isc;
                out[SC_V_OFF + ((gn0+1) * 64 + db + 1) * 3 + x] = v1h[x] * isc;
            }
        }
    }
}

// ===================== K2: edge side — 8x2 tiles, cp.async pipeline ========
#define SA 0
#define SB 8960
#define SW1 17920
#define WS0 18432
#define WS1 22528
#define SMETA 26624
#define K2_SMEM_BYTES (27392 * 4)

// transposed (k-major) activation store with silu; 8 rows per column as 2 float4.
__device__ __forceinline__ void store_actT(float* dst, const u64 Y[4][2],
                                           int nb, int db, float scale) {
#pragma unroll
    for (int c = 0; c < 2; c++) {
        float y0l, y0h, y1l, y1h, y2l, y2h, y3l, y3h;
        unpack2(Y[0][c], y0l, y0h);
        unpack2(Y[1][c], y1l, y1h);
        unpack2(Y[2][c], y2l, y2h);
        unpack2(Y[3][c], y3l, y3h);
        float* base = dst + (db + c) * 140 + nb;
        *(float4*)(base)     = make_float4(silu_f(y0l*scale), silu_f(y0h*scale),
                                           silu_f(y1l*scale), silu_f(y1h*scale));
        *(float4*)(base + 4) = make_float4(silu_f(y2l*scale), silu_f(y2h*scale),
                                           silu_f(y3l*scale), silu_f(y3h*scale));
    }
}

__device__ __forceinline__ void stage_w64(float* dst, const float* src,
                                          int ld_src, int col0, int tid) {
#pragma unroll
    for (int i = tid; i < 1024; i += 512) {
        int k = i >> 4, c4 = (i & 15) * 4;
        cp16(smaddr(dst + k * 64 + c4), src + k * ld_src + col0 + c4);
    }
    cp_commit();
}

__global__ void __launch_bounds__(512, 2) edge_kernel(
    const float* __restrict__ ef_g, const float* __restrict__ sh0_g,
    const float* __restrict__ sh1_g, const int* __restrict__ snd_g,
    const int* __restrict__ rcv_g,
    const float* __restrict__ W1, const float* __restrict__ W2,
    const float* __restrict__ W3, const float* __restrict__ W4) {
    extern __shared__ float sm[];
    const int tid = threadIdx.x;
    const int e0 = blockIdx.x * 128;
    const int tx = tid & 31, ty = tid >> 5;     // ty 0..15 (8-edge rows), tx 0..31 (2-col)
    const int nb = ty * 8, db = tx * 2;
    const int e_loc = tid >> 2, cg = tid & 3, ch = cg * 16;
    const float i3 = rsqrtf(3.0f), i2 = rsqrtf(2.0f), is8 = rsqrtf(8.0f);
    u64 Y[4][2];

    if (tid < 128) {
        int ge = e0 + tid;
        ((int*)(sm + SMETA))[tid]       = snd_g[ge];
        ((int*)(sm + SMETA + 128))[tid] = rcv_g[ge];
        sm[SMETA + 256 + tid] = sh0_g[ge];
        sm[SMETA + 384 + tid] = sh1_g[ge * 3 + 0];
        sm[SMETA + 512 + tid] = sh1_g[ge * 3 + 1];
        sm[SMETA + 640 + tid] = sh1_g[ge * 3 + 2];
    }
    for (int i = tid; i < 1024; i += 512) {
        int e = i >> 3, k = i & 7;
        sm[SA + k * 140 + e] = ef_g[e0 * 8 + i];
    }
    sm[SW1 + tid] = W1[tid];
    stage_w64(sm + WS0, W2, 64, 0, tid);
    stage_w64(sm + WS1, W3, 64, 0, tid);
    __syncthreads();

    gemm8x2<8, 140>(sm + SA + nb, sm + SW1 + db, Y);
    store_actT(sm + SB, Y, nb, db, is8);
    asm volatile("cp.async.wait_group 1;" ::: "memory");
    __syncthreads();

    gemm8x2<64, 140>(sm + SB + nb, sm + WS0 + db, Y);
    store_actT(sm + SA, Y, nb, db, 0.125f);
    asm volatile("cp.async.wait_group 0;" ::: "memory");
    __syncthreads();
    stage_w64(sm + WS0, W4, 320, 0 * 64, tid);

    gemm8x2<64, 140>(sm + SA + nb, sm + WS1 + db, Y);
    store_actT(sm + SB, Y, nb, db, 0.125f);
    __syncthreads();
    stage_w64(sm + WS1, W4, 320, 1 * 64, tid);

    const int s = ((const int*)(sm + SMETA))[e_loc];
    const int r = ((const int*)(sm + SMETA + 128))[e_loc];
    const float sh0v = sm[SMETA + 256 + e_loc];
    const float qx = sm[SMETA + 384 + e_loc];
    const float qy = sm[SMETA + 512 + e_loc];
    const float qz = sm[SMETA + 640 + e_loc];
    const float* sep = g_s_scr + s * 64 + ch;
    const float* vp  = g_v_scr + s * 192 + ch;

#pragma unroll 1
    for (int p = 0; p < 5; p++) {
        float* buf = sm + ((p & 1) ? WS1 : WS0);
        if (p < 4) asm volatile("cp.async.wait_group 1;" ::: "memory");
        else       asm volatile("cp.async.wait_group 0;" ::: "memory");
        __syncthreads();

        gemm8x2<64, 140>(sm + SB + nb, buf + db, Y);
        // path weights -> WSM (=SA), edge-major [128][68], scaled 1/8
#pragma unroll
        for (int rp = 0; rp < 4; rp++) {
            float y0l, y0h, y1l, y1h;
            unpack2(Y[rp][0], y0l, y0h);
            unpack2(Y[rp][1], y1l, y1h);
            int rrow = nb + 2*rp;
            *(float2*)(sm + SA + rrow * 68 + db)       = make_float2(y0l*0.125f, y1l*0.125f);
            *(float2*)(sm + SA + (rrow + 1) * 68 + db) = make_float2(y0h*0.125f, y1h*0.125f);
        }
        __syncthreads();
        if (p + 2 <= 4) stage_w64(buf, W4, 320, (p + 2) * 64, tid);

        const float* wrow = sm + SA + e_loc * 68 + ch;
        if (p == 0) {
            float* dst = g_ms + r * 128 + ch;
#pragma unroll
            for (int g = 0; g < 4; g++) {
                float4 wv = *(const float4*)(wrow + g*4);
                float4 se = *(const float4*)(sep + g*4);
                red4v(dst + g*4, f4muls(f4mul(wv, se), sh0v));
            }
        } else if (p == 1) {
            float* dst = g_ms + r * 128 + 64 + ch;
#pragma unroll
            for (int g = 0; g < 4; g++) {
                float4 wv = *(const float4*)(wrow + g*4);
                float4 vx = *(const float4*)(vp + g*4);
                float4 vy = *(const float4*)(vp + 64 + g*4);
                float4 vz = *(const float4*)(vp + 128 + g*4);
                float4 dt = f4add(f4add(f4muls(vx, qx), f4muls(vy, qy)), f4muls(vz, qz));
                red4v(dst + g*4, f4muls(f4mul(wv, dt), i3));
            }
        } else if (p == 2) {
            float* dst = g_mv + r * 576 + ch * 3;
            float4 aqx = make_float4(qx,qx,qx,qx);
            float4 aqy = make_float4(qy,qy,qy,qy);
            float4 aqz = make_float4(qz,qz,qz,qz);
#pragma unroll
            for (int g = 0; g < 4; g++) {
                float4 wv = *(const float4*)(wrow + g*4);
                float4 se = *(const float4*)(sep + g*4);
                scatter_vec_group(dst + g*12, f4mul(wv, se), aqx, aqy, aqz);
            }
        } else if (p == 3) {
            float* dst = g_mv + r * 576 + 192 + ch * 3;
#pragma unroll
            for (int g = 0; g < 4; g++) {
                float4 wv = *(const float4*)(wrow + g*4);
                float4 vx = *(const float4*)(vp + g*4);
                float4 vy = *(const float4*)(vp + 64 + g*4);
                float4 vz = *(const float4*)(vp + 128 + g*4);
                scatter_vec_group(dst + g*12, f4muls(wv, sh0v), vx, vy, vz);
            }
        } else {
            float* dst = g_mv + r * 576 + 384 + ch * 3;
#pragma unroll
            for (int g = 0; g < 4; g++) {
                float4 wv = *(const float4*)(wrow + g*4);
                float4 vx = *(const float4*)(vp + g*4);
                float4 vy = *(const float4*)(vp + 64 + g*4);
                float4 vz = *(const float4*)(vp + 128 + g*4);
                float4 crx = f4sub(f4muls(vy, qz), f4muls(vz, qy));
                float4 cry = f4sub(f4muls(vz, qx), f4muls(vx, qz));
                float4 crz = f4sub(f4muls(vx, qy), f4muls(vy, qx));
                scatter_vec_group(dst + g*12, f4muls(wv, i2), crx, cry, crz);
            }
        }
    }
}

// ===================== K3: output linear — 8x2 tiles =====================
#define K3_SMEM_BYTES (25344 * 4)
__global__ void __launch_bounds__(256, 2) out_kernel(
    const float* __restrict__ Wouts, const float* __restrict__ Woutv,
    float* __restrict__ out) {
    extern __shared__ float sm[];
    float* msm = sm;
    float* wbuf = sm + 13056;
    const int tid = threadIdx.x;
    const int n0 = blockIdx.x * 64;
    const int tx = tid & 31, ty = tid >> 5;   // ty 0..7 (8-row), tx 0..31 (2-col)
    const int nb = ty * 8, db = tx * 2;
    u64 Y[4][2];

    for (int idx = tid; idx < 8192; idx += 256) {
        int n = idx >> 7, k = idx & 127, gn = n0 + n;
        msm[k * 68 + n] = (gn < NNODES) ? g_ms[gn * 128 + k] : 0.0f;
    }
    for (int idx = tid; idx < 8192; idx += 256) wbuf[idx] = Wouts[idx];
    __syncthreads();
    gemm8x2<128, 68>(msm + nb, wbuf + db, Y);
    const float ss = rsqrtf(128.0f) / 16.0f;
#pragma unroll
    for (int rp = 0; rp < 4; rp++) {
        float y0l, y0h, y1l, y1h;
        unpack2(Y[rp][0], y0l, y0h);
        unpack2(Y[rp][1], y1l, y1h);
        int gn0 = n0 + nb + 2*rp;
        if (gn0 < NNODES)
            *(float2*)(out + gn0 * 64 + db) = make_float2(y0l*ss, y1l*ss);
        if (gn0 + 1 < NNODES)
            *(float2*)(out + (gn0+1) * 64 + db) = make_float2(y0h*ss, y1h*ss);
    }
    __syncthreads();
    for (int idx = tid; idx < 12288; idx += 256) wbuf[idx] = Woutv[idx];
    const float sv = rsqrtf(192.0f) / 16.0f;
#pragma unroll 1
    for (int x = 0; x < 3; x++) {
        __syncthreads();
        for (int idx = tid; idx < 12288; idx += 256) {
            int n = idx / 192, k = idx - n * 192, gn = n0 + n;
            msm[k * 68 + n] = (gn < NNODES) ? g_mv[gn * 576 + k * 3 + x] : 0.0f;
        }
        __syncthreads();
        gemm8x2<192, 68>(msm + nb, wbuf + db, Y);
#pragma unroll
        for (int rp = 0; rp < 4; rp++) {
            float y0l, y0h, y1l, y1h;
            unpack2(Y[rp][0], y0l, y0h);
            unpack2(Y[rp][1], y1l, y1h);
            int gn0 = n0 + nb + 2*rp;
            if (gn0 < NNODES) {
                out[OUT_V_OFF + gn0 * 192 + db * 3 + x]       = y0l * sv;
                out[OUT_V_OFF + gn0 * 192 + (db + 1) * 3 + x] = y1l * sv;
            }
            if (gn0 + 1 < NNODES) {
                out[OUT_V_OFF + (gn0+1) * 192 + db * 3 + x]       = y0h * sv;
                out[OUT_V_OFF + (gn0+1) * 192 + (db + 1) * 3 + x] = y1h * sv;
            }
        }
    }
}

// ===================== launch =====================
extern "C" void kernel_launch(void* const* d_in, const int* in_sizes, int n_in,
                              void* d_out, int out_size) {
    const float* attrs = (const float*)d_in[0];
    const float* fs    = (const float*)d_in[1];
    const float* fv    = (const float*)d_in[2];
    const float* sh0   = (const float*)d_in[3];
    const float* sh1   = (const float*)d_in[4];
    const float* ef    = (const float*)d_in[5];
    const int*   snd   = (const int*)d_in[6];
    const int*   rcv   = (const int*)d_in[7];
    const float* Wscs  = (const float*)d_in[8];
    const float* Wscv  = (const float*)d_in[9];
    const float* Wses  = (const float*)d_in[10];
    const float* Wsev  = (const float*)d_in[11];
    const float* W1    = (const float*)d_in[12];
    const float* W2    = (const float*)d_in[13];
    const float* W3    = (const float*)d_in[14];
    const float* W4    = (const float*)d_in[15];
    const float* Wouts = (const float*)d_in[16];
    const float* Woutv = (const float*)d_in[17];
    float* out = (float*)d_out;

    cudaFuncSetAttribute(node_kernel, cudaFuncAttributeMaxDynamicSharedMemorySize, K1_SMEM_BYTES);
    cudaFuncSetAttribute(edge_kernel, cudaFuncAttributeMaxDynamicSharedMemorySize, K2_SMEM_BYTES);
    cudaFuncSetAttribute(out_kernel,  cudaFuncAttributeMaxDynamicSharedMemorySize, K3_SMEM_BYTES);

    zero_kernel<<<1024, 256>>>();
    node_kernel<<<(NNODES + NTILE - 1) / NTILE, 512, K1_SMEM_BYTES>>>(
        attrs, fs, fv, Wscs, Wscv, Wses, Wsev, out);
    edge_kernel<<<NEDGES / 128, 512, K2_SMEM_BYTES>>>(
        ef, sh0, sh1, snd, rcv, W1, W2, W3, W4);
    out_kernel<<<(NNODES + 63) / 64, 256, K3_SMEM_BYTES>>>(Wouts, Woutv, out);
}